// round 16
// baseline (speedup 1.0000x reference)
#include <cuda_runtime.h>
#include <cuda_bf16.h>
#include <math.h>
#include <stdint.h>

#define B_  4
#define T_  1024
#define C_  1024
#define H_  16
#define DH_ 64
#define BH_ 64            // B_*H_
#define M_  4096          // B_*T_

// ---------------- scratch (device globals: allocation-free) ----------------
__device__ float g_q[BH_ * T_ * DH_];       // fp32 q after projection
__device__ float g_epart[BH_ * 16];
__device__ float g_mask[BH_];

// bf16 split buffers
__device__ __nv_bfloat16 g_xh[M_ * C_],  g_xl[M_ * C_], g_x3[M_ * C_];
__device__ __nv_bfloat16 g_qws[C_ * C_];
__device__ __nv_bfloat16 g_kwh[C_ * C_], g_kwl[C_ * C_];
__device__ __nv_bfloat16 g_vwh[C_ * C_], g_vwl[C_ * C_];
__device__ __nv_bfloat16 g_owh[C_ * C_], g_owl[C_ * C_];
__device__ __nv_bfloat16 g_aoh[M_ * C_], g_aol[M_ * C_];
// attention operand splits
__device__ __nv_bfloat16 g_qsh[BH_ * T_ * DH_], g_qsl[BH_ * T_ * DH_];   // (bh,t,d)
__device__ __nv_bfloat16 g_ksh[BH_ * T_ * DH_], g_ksl[BH_ * T_ * DH_];   // (bh,t,d)
__device__ __nv_bfloat16 g_vth[BH_ * T_ * DH_], g_vtl[BH_ * T_ * DH_];   // (bh,d,t)

__constant__ int KEEPC[16] = {22,21,20,19,18,18,17,16,15,14,13,13,12,11,10,9};

// ---------------- helpers ----------------
__device__ __forceinline__ void twosum(float& s, float& c, float v) {
    float t  = __fadd_rn(s, v);
    float bo = __fsub_rn(t, s);
    float e1 = __fsub_rn(s, __fsub_rn(t, bo));
    float e2 = __fsub_rn(v, bo);
    c = __fadd_rn(c, __fadd_rn(e1, e2));
    s = t;
}

// fast exp (no MUFU): d <= 0, rel err ~2.4e-8
__device__ __forceinline__ float fast_exp(float d) {
    d = fmaxf(d, -80.f);
    float t = d * 1.4426950408889634f;
    float n = rintf(t);
    float f = fmaf(n, -0.693147182464599609375f, d);
    f = fmaf(n, 1.9046542999577680452e-9f, f);
    float p = 1.3888888888888889e-3f;
    p = fmaf(p, f, 8.3333333333333332e-3f);
    p = fmaf(p, f, 4.1666666666666664e-2f);
    p = fmaf(p, f, 1.6666666666666666e-1f);
    p = fmaf(p, f, 0.5f);
    p = fmaf(p, f, 1.0f);
    p = fmaf(p, f, 1.0f);
    int j = (int)n;
    return p * __uint_as_float((unsigned)(127 + j) << 23);
}

__device__ __forceinline__ uint32_t pack_bf16x2(float lo, float hi) {
    uint32_t r;
    asm("cvt.rn.bf16x2.f32 %0, %1, %2;" : "=r"(r) : "f"(hi), "f"(lo));
    return r;
}

__device__ __forceinline__ void mma16816(float* d,
    uint32_t a0, uint32_t a1, uint32_t a2, uint32_t a3,
    uint32_t b0, uint32_t b1)
{
    asm volatile(
        "mma.sync.aligned.m16n8k16.row.col.f32.bf16.bf16.f32 "
        "{%0,%1,%2,%3}, {%4,%5,%6,%7}, {%8,%9}, {%0,%1,%2,%3};"
        : "+f"(d[0]), "+f"(d[1]), "+f"(d[2]), "+f"(d[3])
        : "r"(a0), "r"(a1), "r"(a2), "r"(a3), "r"(b0), "r"(b1));
}

__device__ __forceinline__ void ldsm4(uint32_t addr,
    uint32_t& r0, uint32_t& r1, uint32_t& r2, uint32_t& r3)
{
    asm volatile("ldmatrix.sync.aligned.m8n8.x4.shared.b16 {%0,%1,%2,%3}, [%4];"
                 : "=r"(r0), "=r"(r1), "=r"(r2), "=r"(r3) : "r"(addr));
}

__device__ __forceinline__ void bf16split(float x, unsigned short& h, unsigned short& l) {
    __nv_bfloat16 hh = __float2bfloat16(x);
    h = __bfloat16_as_ushort(hh);
    l = __bfloat16_as_ushort(__float2bfloat16(x - __bfloat162float(hh)));
}

// ---------------- fused prep: split3x (x) + wsplit4 (weights) in one launch ----------------
__global__ void prep_fused(const float4* __restrict__ x,
                           const float4* __restrict__ kw, const float4* __restrict__ vw,
                           const float4* __restrict__ ow, const float4* __restrict__ qw,
                           ushort4* __restrict__ xh, ushort4* __restrict__ xl,
                           ushort4* __restrict__ x3,
                           ushort4* __restrict__ kwh, ushort4* __restrict__ kwl,
                           ushort4* __restrict__ vwh, ushort4* __restrict__ vwl,
                           ushort4* __restrict__ owh, ushort4* __restrict__ owl,
                           ushort4* __restrict__ qws)
{
    int bid = blockIdx.x;
    if (bid < M_ * C_ / 1024) {                       // x 3-term split
        int i = bid * 256 + threadIdx.x;
        float4 v = x[i];
        float a[4] = {v.x, v.y, v.z, v.w};
        ushort4 H, L, T3;
        unsigned short* hp = &H.x; unsigned short* lp = &L.x; unsigned short* tp = &T3.x;
#pragma unroll
        for (int j = 0; j < 4; j++) {
            __nv_bfloat16 h = __float2bfloat16(a[j]);
            float r1 = a[j] - __bfloat162float(h);
            __nv_bfloat16 l = __float2bfloat16(r1);
            float r2 = r1 - __bfloat162float(l);
            tp[j] = __bfloat16_as_ushort(__float2bfloat16(r2));
            hp[j] = __bfloat16_as_ushort(h);
            lp[j] = __bfloat16_as_ushort(l);
        }
        xh[i] = H; xl[i] = L; x3[i] = T3;
        return;
    }
    int u = bid - M_ * C_ / 1024;                     // 0..4095
    int which = u >> 10;                              // 0 kw, 1 vw, 2 ow, 3 qw-sign
    int i = (u & 1023) * 256 + threadIdx.x;
    if (which == 3) {
        float4 v = qw[i];
        ushort4 o;
        o.x = (v.x > 0.f) ? 0x3F80 : ((v.x < 0.f) ? 0xBF80 : 0);
        o.y = (v.y > 0.f) ? 0x3F80 : ((v.y < 0.f) ? 0xBF80 : 0);
        o.z = (v.z > 0.f) ? 0x3F80 : ((v.z < 0.f) ? 0xBF80 : 0);
        o.w = (v.w > 0.f) ? 0x3F80 : ((v.w < 0.f) ? 0xBF80 : 0);
        qws[i] = o;
        return;
    }
    const float4* src = (which == 0) ? kw : (which == 1) ? vw : ow;
    ushort4* hi = (which == 0) ? kwh : (which == 1) ? vwh : owh;
    ushort4* lo = (which == 0) ? kwl : (which == 1) ? vwl : owl;
    float4 v = src[i];
    float a[4] = {v.x, v.y, v.z, v.w};
    ushort4 H, L;
    unsigned short* hp = &H.x; unsigned short* lp = &L.x;
#pragma unroll
    for (int j = 0; j < 4; j++) bf16split(a[j], hp[j], lp[j]);
    hi[i] = H; lo[i] = L;
}

// ---------------- shared GEMM mainloop pieces (128x128, 2 CTA/SM) ----------------
#define TILE_B   10240
#define STAGE_B  40960
#define NCHUNK   32

__device__ __forceinline__ void load_chunk_async(
    uint32_t sbase,
    const __nv_bfloat16* __restrict__ Ahi, const __nv_bfloat16* __restrict__ Alo,
    const __nv_bfloat16* __restrict__ Bhi, const __nv_bfloat16* __restrict__ Blo,
    int m0, int n0, int k0, int tid)
{
#pragma unroll
    for (int i = 0; i < 8; i++) {
        int u = tid + i * 256;
        int tile = u >> 9;
        int idx = u & 511;
        int row = idx >> 2;
        int jj = idx & 3;
        const __nv_bfloat16* g;
        if (tile == 0)      g = Ahi + (size_t)(m0 + row) * C_ + k0 + jj * 8;
        else if (tile == 1) g = Alo + (size_t)(m0 + row) * C_ + k0 + jj * 8;
        else if (tile == 2) g = Bhi + (size_t)(n0 + row) * C_ + k0 + jj * 8;
        else                g = Blo + (size_t)(n0 + row) * C_ + k0 + jj * 8;
        uint32_t dst = sbase + tile * TILE_B + row * 80 + jj * 16;
        asm volatile("cp.async.cg.shared.global [%0], [%1], 16;" :: "r"(dst), "l"(g));
    }
}

// MMA pass order: for each K-slab, all Ah*Bh, then all Al*Bh, then all Ah*Bl.
// Per-accumulator contribution ORDER is unchanged (hi*hi, lo*hi, hi*lo) ->
// bitwise identical to the fused-trio version, but RAW chains are broken.
#define GEMM_MAINLOOP(ACT_EXPR, NA)                                                   \
    const uint32_t aBase = (uint32_t)((wm * 64 + (lane & 7) + ((lane >> 3) & 1) * 8) * 80 \
                                      + ((lane >> 4) & 1) * 16);                      \
    const uint32_t bBase = (uint32_t)((wn * 32 + (lane & 7) + ((lane >> 4) & 1) * 8) * 80 \
                                      + ((lane >> 3) & 1) * 16);                      \
    load_chunk_async(sbase, Ahi, Alo, Bhi, Blo, m0, n0, (ACT_EXPR(0)) * 32, tid);     \
    asm volatile("cp.async.commit_group;" ::: "memory");                              \
    asm volatile("cp.async.wait_group 0;" ::: "memory");                              \
    __syncthreads();                                                                  \
    for (int c = 0; c < (NA); c++) {                                                  \
        if (c + 1 < (NA)) {                                                           \
            load_chunk_async(sbase + ((c + 1) & 1) * STAGE_B,                         \
                             Ahi, Alo, Bhi, Blo, m0, n0, (ACT_EXPR(c + 1)) * 32, tid);\
            asm volatile("cp.async.commit_group;" ::: "memory");                      \
        }                                                                             \
        const uint32_t stw = sbase + (c & 1) * STAGE_B;                               \
        _Pragma("unroll")                                                             \
        for (int ks = 0; ks < 2; ks++) {                                              \
            const uint32_t kb = ks * 32;                                              \
            uint32_t ah[4][4], al[4][4], bhf[4][2], blf[4][2];                        \
            ldsm4(stw + 2 * TILE_B + bBase + kb,                                      \
                  bhf[0][0], bhf[0][1], bhf[1][0], bhf[1][1]);                        \
            ldsm4(stw + 2 * TILE_B + 1280 + bBase + kb,                               \
                  bhf[2][0], bhf[2][1], bhf[3][0], bhf[3][1]);                        \
            ldsm4(stw + 3 * TILE_B + bBase + kb,                                      \
                  blf[0][0], blf[0][1], blf[1][0], blf[1][1]);                        \
            ldsm4(stw + 3 * TILE_B + 1280 + bBase + kb,                               \
                  blf[2][0], blf[2][1], blf[3][0], blf[3][1]);                        \
            _Pragma("unroll")                                                         \
            for (int mt = 0; mt < 4; mt++) {                                          \
                ldsm4(stw + aBase + mt * 1280 + kb,                                   \
                      ah[mt][0], ah[mt][1], ah[mt][2], ah[mt][3]);                    \
                ldsm4(stw + TILE_B + aBase + mt * 1280 + kb,                          \
                      al[mt][0], al[mt][1], al[mt][2], al[mt][3]);                    \
            }                                                                         \
            _Pragma("unroll")                                                         \
            for (int mt = 0; mt < 4; mt++)                                            \
                _Pragma("unroll")                                                     \
                for (int nt = 0; nt < 4; nt++)                                        \
                    mma16816(acc[mt][nt], ah[mt][0], ah[mt][1], ah[mt][2], ah[mt][3], \
                             bhf[nt][0], bhf[nt][1]);                                 \
            _Pragma("unroll")                                                         \
            for (int mt = 0; mt < 4; mt++)                                            \
                _Pragma("unroll")                                                     \
                for (int nt = 0; nt < 4; nt++)                                        \
                    mma16816(acc[mt][nt], al[mt][0], al[mt][1], al[mt][2], al[mt][3], \
                             bhf[nt][0], bhf[nt][1]);                                 \
            _Pragma("unroll")                                                         \
            for (int mt = 0; mt < 4; mt++)                                            \
                _Pragma("unroll")                                                     \
                for (int nt = 0; nt < 4; nt++)                                        \
                    mma16816(acc[mt][nt], ah[mt][0], ah[mt][1], ah[mt][2], ah[mt][3], \
                             blf[nt][0], blf[nt][1]);                                 \
        }                                                                             \
        if (c + 1 < (NA))                                                             \
            asm volatile("cp.async.wait_group 0;" ::: "memory");                      \
        __syncthreads();                                                              \
    }

#define ACT_ID(c) (c)
#define ACT_LUT(c) (act[c])

#define QTILE_B  5120
#define QSTAGE_B 25600
#define QNCH     32

__device__ __forceinline__ void qload_chunk_async(
    uint32_t sbase,
    const __nv_bfloat16* __restrict__ X1, const __nv_bfloat16* __restrict__ X2,
    const __nv_bfloat16* __restrict__ X3, const __nv_bfloat16* __restrict__ Ws,
    int m0, int n0, int k0, int tid)
{
#pragma unroll
    for (int i = 0; i < 5; i++) {
        int u = tid + i * 256;
        const __nv_bfloat16* g;
        uint32_t dst;
        if (u < 768) {
            int term = u >> 8;
            int idx = u & 255;
            int row = idx >> 2, jj = idx & 3;
            const __nv_bfloat16* base = (term == 0) ? X1 : (term == 1) ? X2 : X3;
            g = base + (size_t)(m0 + row) * C_ + k0 + jj * 8;
            dst = sbase + term * QTILE_B + row * 80 + jj * 16;
        } else {
            int v = u - 768;
            int row = v >> 2, jj = v & 3;
            g = Ws + (size_t)(n0 + row) * C_ + k0 + jj * 8;
            dst = sbase + 3 * QTILE_B + row * 80 + jj * 16;
        }
        asm volatile("cp.async.cg.shared.global [%0], [%1], 16;" :: "r"(dst), "l"(g));
    }
}

// ---------------- fused projection kernel: K (0-255) | V (256-511) | Q (512-1023) ----------------
__global__ __launch_bounds__(256) void proj_fused(
    const __nv_bfloat16* __restrict__ xh, const __nv_bfloat16* __restrict__ xl,
    const __nv_bfloat16* __restrict__ x3, const __nv_bfloat16* __restrict__ qws,
    const __nv_bfloat16* __restrict__ kwh, const __nv_bfloat16* __restrict__ kwl,
    const __nv_bfloat16* __restrict__ vwh, const __nv_bfloat16* __restrict__ vwl,
    const float* __restrict__ qb, const float* __restrict__ kb, const float* __restrict__ vb,
    float* __restrict__ Q,
    __nv_bfloat16* __restrict__ kh, __nv_bfloat16* __restrict__ kl,
    __nv_bfloat16* __restrict__ vth, __nv_bfloat16* __restrict__ vtl)
{
    extern __shared__ char smc[];
    const int tid = threadIdx.x;
    const int lane = tid & 31, wid = tid >> 5;
    const int wm = wid >> 2, wn = wid & 3;
    const int gID = lane >> 2, tg = lane & 3;
    uint32_t sbase = (uint32_t)__cvta_generic_to_shared(smc);
    const int bid = blockIdx.x;

    if (bid < 512) {
        // ---------------- K or V path ----------------
        const int isV = (bid >= 256);
        const int lb = bid & 255;
        const int m0 = (lb >> 3) * 128, n0 = (lb & 7) * 128;
        const __nv_bfloat16* Ahi = xh;
        const __nv_bfloat16* Alo = xl;
        const __nv_bfloat16* Bhi = isV ? vwh : kwh;
        const __nv_bfloat16* Blo = isV ? vwl : kwl;
        const float* bias = isV ? vb : kb;

        float acc[4][4][4];
#pragma unroll
        for (int mt = 0; mt < 4; mt++)
#pragma unroll
            for (int nt = 0; nt < 4; nt++)
#pragma unroll
                for (int r = 0; r < 4; r++) acc[mt][nt][r] = 0.f;

        GEMM_MAINLOOP(ACT_ID, NCHUNK)

        if (!isV) {
            float* tb = (float*)smc;     // [128][132]
#pragma unroll
            for (int mt = 0; mt < 4; mt++) {
                int ml = wm * 64 + mt * 16 + gID;
#pragma unroll
                for (int nt = 0; nt < 4; nt++) {
                    int nl = wn * 32 + nt * 8 + tg * 2;
                    float b0v = bias[n0 + nl], b1v = bias[n0 + nl + 1];
                    tb[ml * 132 + nl]           = acc[mt][nt][0] + b0v;
                    tb[ml * 132 + nl + 1]       = acc[mt][nt][1] + b1v;
                    tb[(ml + 8) * 132 + nl]     = acc[mt][nt][2] + b0v;
                    tb[(ml + 8) * 132 + nl + 1] = acc[mt][nt][3] + b1v;
                }
            }
            __syncthreads();
            {
                int ml = tid >> 1, h2 = tid & 1;
                const float* row = &tb[ml * 132 + h2 * 64];
                float ss = 0.f;
#pragma unroll
                for (int j4 = 0; j4 < 16; j4++) {
                    float4 v = *(const float4*)&row[j4 * 4];
                    ss += v.x * v.x + v.y * v.y + v.z * v.z + v.w * v.w;
                }
                float inv = 1.f / (sqrtf(ss * (1.f / 64.f)) + 1e-6f);
                int m = m0 + ml;
                int bb = m >> 10, t = m & 1023;
                int h = (n0 >> 6) + h2;
                __nv_bfloat16* oh = kh + (((size_t)(bb * H_ + h)) * T_ + t) * DH_;
                __nv_bfloat16* ol = kl + (((size_t)(bb * H_ + h)) * T_ + t) * DH_;
#pragma unroll
                for (int j4 = 0; j4 < 16; j4++) {
                    float4 v = *(const float4*)&row[j4 * 4];
                    ushort4 Hv, Lv;
                    bf16split(v.x * inv, Hv.x, Lv.x);
                    bf16split(v.y * inv, Hv.y, Lv.y);
                    bf16split(v.z * inv, Hv.z, Lv.z);
                    bf16split(v.w * inv, Hv.w, Lv.w);
                    *(ushort4*)&oh[j4 * 4] = Hv;
                    *(ushort4*)&ol[j4 * 4] = Lv;
                }
            }
        } else {
            float* tb = (float*)smc;     // [128][132] transposed
#pragma unroll
            for (int mt = 0; mt < 4; mt++) {
                int ml = wm * 64 + mt * 16 + gID;
#pragma unroll
                for (int nt = 0; nt < 4; nt++) {
                    int nl = wn * 32 + nt * 8 + tg * 2;
                    float b0v = bias[n0 + nl], b1v = bias[n0 + nl + 1];
                    tb[nl * 132 + ml]           = acc[mt][nt][0] + b0v;
                    tb[(nl + 1) * 132 + ml]     = acc[mt][nt][1] + b1v;
                    tb[nl * 132 + ml + 8]       = acc[mt][nt][2] + b0v;
                    tb[(nl + 1) * 132 + ml + 8] = acc[mt][nt][3] + b1v;
                }
            }
            __syncthreads();
            {
                int nl = tid >> 1, mhalf = (tid & 1) * 64;
                const float* row = &tb[nl * 132 + mhalf];
                int h = (n0 >> 6) + (nl >> 6);
                int d = nl & 63;
                int bb = m0 >> 10;
                int t0 = (m0 & 1023) + mhalf;
                __nv_bfloat16* oh = vth + (((size_t)(bb * H_ + h)) * DH_ + d) * T_ + t0;
                __nv_bfloat16* ol = vtl + (((size_t)(bb * H_ + h)) * DH_ + d) * T_ + t0;
#pragma unroll
                for (int j4 = 0; j4 < 16; j4++) {
                    float4 v = *(const float4*)&row[j4 * 4];
                    ushort4 Hv, Lv;
                    bf16split(v.x, Hv.x, Lv.x);
                    bf16split(v.y, Hv.y, Lv.y);
                    bf16split(v.z, Hv.z, Lv.z);
                    bf16split(v.w, Hv.w, Lv.w);
                    *(ushort4*)&oh[j4 * 4] = Hv;
                    *(ushort4*)&ol[j4 * 4] = Lv;
                }
            }
        }
    } else {
        // ---------------- Q path (exact 3-term split + chunked TwoSum): 64x128 ----------------
        const int qid = bid - 512;                   // 0..511
        const int m0 = (qid >> 3) * 64, n0 = (qid & 7) * 128;

        const uint32_t aQBase = (uint32_t)((wm * 32 + (lane & 7) + ((lane >> 3) & 1) * 8) * 80
                                           + ((lane >> 4) & 1) * 16);
        const uint32_t bQBase = (uint32_t)((wn * 32 + (lane & 7) + ((lane >> 4) & 1) * 8) * 80
                                           + ((lane >> 3) & 1) * 16);

        float s_[2][4][4], c_[2][4][4];
#pragma unroll
        for (int mt = 0; mt < 2; mt++)
#pragma unroll
            for (int nt = 0; nt < 4; nt++)
#pragma unroll
                for (int r = 0; r < 4; r++) { s_[mt][nt][r] = 0.f; c_[mt][nt][r] = 0.f; }

        qload_chunk_async(sbase, xh, xl, x3, qws, m0, n0, 0, tid);
        asm volatile("cp.async.commit_group;" ::: "memory");
        asm volatile("cp.async.wait_group 0;" ::: "memory");
        __syncthreads();

        for (int c = 0; c < QNCH; c++) {
            if (c + 1 < QNCH) {
                qload_chunk_async(sbase + ((c + 1) & 1) * QSTAGE_B,
                                  xh, xl, x3, qws, m0, n0, (c + 1) * 32, tid);
                asm volatile("cp.async.commit_group;" ::: "memory");
            }
            const uint32_t stq = sbase + (c & 1) * QSTAGE_B;

            float tacc[2][4][4];
#pragma unroll
            for (int mt = 0; mt < 2; mt++)
#pragma unroll
                for (int nt = 0; nt < 4; nt++)
#pragma unroll
                    for (int r = 0; r < 4; r++) tacc[mt][nt][r] = 0.f;

#pragma unroll
            for (int ks = 0; ks < 2; ks++) {
                const uint32_t kb = ks * 32;
                uint32_t bw[4][2];
                ldsm4(stq + 3 * QTILE_B + bQBase + kb,
                      bw[0][0], bw[0][1], bw[1][0], bw[1][1]);
                ldsm4(stq + 3 * QTILE_B + 1280 + bQBase + kb,
                      bw[2][0], bw[2][1], bw[3][0], bw[3][1]);
#pragma unroll
                for (int term = 0; term < 3; term++) {
                    uint32_t ah[2][4];
#pragma unroll
                    for (int mt = 0; mt < 2; mt++)
                        ldsm4(stq + term * QTILE_B + aQBase + mt * 1280 + kb,
                              ah[mt][0], ah[mt][1], ah[mt][2], ah[mt][3]);
#pragma unroll
                    for (int mt = 0; mt < 2; mt++)
#pragma unroll
                        for (int nt = 0; nt < 4; nt++)
                            mma16816(tacc[mt][nt], ah[mt][0], ah[mt][1], ah[mt][2], ah[mt][3],
                                     bw[nt][0], bw[nt][1]);
                }
            }
#pragma unroll
            for (int mt = 0; mt < 2; mt++)
#pragma unroll
                for (int nt = 0; nt < 4; nt++)
#pragma unroll
                    for (int r = 0; r < 4; r++)
                        twosum(s_[mt][nt][r], c_[mt][nt][r], tacc[mt][nt][r]);

            if (c + 1 < QNCH)
                asm volatile("cp.async.wait_group 0;" ::: "memory");
            __syncthreads();
        }

#pragma unroll
        for (int mt = 0; mt < 2; mt++) {
            int m1 = m0 + wm * 32 + mt * 16 + gID;
#pragma unroll
            for (int nt = 0; nt < 4; nt++) {
                int n = n0 + wn * 32 + nt * 8 + tg * 2;
                int h = n >> 6, d = n & 63;
                float b0v = qb[n], b1v = qb[n + 1];
                float v0 = __fadd_rn(__fadd_rn(s_[mt][nt][0], c_[mt][nt][0]), b0v);
                float v1 = __fadd_rn(__fadd_rn(s_[mt][nt][1], c_[mt][nt][1]), b1v);
                float v2 = __fadd_rn(__fadd_rn(s_[mt][nt][2], c_[mt][nt][2]), b0v);
                float v3 = __fadd_rn(__fadd_rn(s_[mt][nt][3], c_[mt][nt][3]), b1v);
                int bb = m1 >> 10, t = m1 & 1023;
                *(float2*)&Q[(((size_t)(bb * H_ + h)) * T_ + t) * DH_ + d] = make_float2(v0, v1);
                int m2 = m1 + 8;
                int bb2 = m2 >> 10, t2 = m2 & 1023;
                *(float2*)&Q[(((size_t)(bb2 * H_ + h)) * T_ + t2) * DH_ + d] = make_float2(v2, v3);
            }
        }
    }
}

// ---------------- O GEMM with head-mask chunk skip ----------------
__global__ __launch_bounds__(256) void gemm_o(
    const __nv_bfloat16* __restrict__ Ahi, const __nv_bfloat16* __restrict__ Alo,
    const __nv_bfloat16* __restrict__ Bhi, const __nv_bfloat16* __restrict__ Blo,
    const float* __restrict__ bias, float* __restrict__ Cout,
    const float* __restrict__ maskp)
{
    extern __shared__ char smc[];
    const int tid = threadIdx.x;
    const int lane = tid & 31, wid = tid >> 5;
    const int wm = wid >> 2, wn = wid & 3;
    const int gID = lane >> 2, tg = lane & 3;
    const int m0 = blockIdx.y * 128, n0 = blockIdx.x * 128;
    uint32_t sbase = (uint32_t)__cvta_generic_to_shared(smc);

    __shared__ int act[NCHUNK];
    __shared__ int s_na;
    if (tid == 0) {
        int n = 0;
        int b16 = (m0 >> 10) << 4;
        for (int ch = 0; ch < NCHUNK; ch++)
            if (maskp[b16 + (ch >> 1)] != 0.f) act[n++] = ch;
        s_na = n;
    }
    __syncthreads();
    const int na = s_na;

    float acc[4][4][4];
#pragma unroll
    for (int mt = 0; mt < 4; mt++)
#pragma unroll
        for (int nt = 0; nt < 4; nt++)
#pragma unroll
            for (int r = 0; r < 4; r++) acc[mt][nt][r] = 0.f;

    GEMM_MAINLOOP(ACT_LUT, na)

#pragma unroll
    for (int mt = 0; mt < 4; mt++) {
        int m1 = m0 + wm * 64 + mt * 16 + gID;
#pragma unroll
        for (int nt = 0; nt < 4; nt++) {
            int n = n0 + wn * 32 + nt * 8 + tg * 2;
            float b0v = bias[n], b1v = bias[n + 1];
            float* a = acc[mt][nt];
            *(float2*)&Cout[(size_t)m1 * C_ + n] = make_float2(a[0] + b0v, a[1] + b1v);
            *(float2*)&Cout[(size_t)(m1 + 8) * C_ + n] = make_float2(a[2] + b0v, a[3] + b1v);
        }
    }
}

// -------------- q post: RMS norm + exact top-k, emits bf16 split --------------
__global__ __launch_bounds__(256) void qpost(
    const float* __restrict__ q,
    __nv_bfloat16* __restrict__ qh, __nv_bfloat16* __restrict__ ql)
{
    int grp = threadIdx.x >> 6;
    int lane = threadIdx.x & 63;
    int row = blockIdx.x * 4 + grp;
    float v = q[(size_t)row * 64 + lane];
    float ss = v * v;
#pragma unroll
    for (int o = 16; o > 0; o >>= 1) ss += __shfl_xor_sync(0xffffffffu, ss, o);
    __shared__ float ws[8];
    if ((threadIdx.x & 31) == 0) ws[threadIdx.x >> 5] = ss;
    __syncthreads();
    float rms = sqrtf((ws[grp * 2] + ws[grp * 2 + 1]) * (1.f / 64.f)) + 1e-6f;
    float vn = v / rms;
    float a = fabsf(vn);
    __shared__ __align__(16) float sa[4][64];
    sa[grp][lane] = a;
    __syncthreads();
    int g = 0;
    const float4* sv = (const float4*)sa[grp];
#pragma unroll
    for (int j = 0; j < 16; j++) {
        float4 t = sv[j];
        g += (t.x > a) + (t.y > a) + (t.z > a) + (t.w > a);
    }
    int h = (row >> 10) & 15;
    int kc = KEEPC[h];
    float cand = (g <= kc - 1) ? a : INFINITY;
#pragma unroll
    for (int o = 16; o > 0; o >>= 1)
        cand = fminf(cand, __shfl_xor_sync(0xffffffffu, cand, o));
    __shared__ float wm_[8];
    if ((threadIdx.x & 31) == 0) wm_[threadIdx.x >> 5] = cand;
    __syncthreads();
    float th = fminf(wm_[grp * 2], wm_[grp * 2 + 1]);
    float vnm = (a >= th) ? vn : 0.f;
    __nv_bfloat16 hh = __float2bfloat16(vnm);
    qh[(size_t)row * 64 + lane] = hh;
    ql[(size_t)row * 64 + lane] = __float2bfloat16(vnm - __bfloat162float(hh));
}

// -------------- MMA flash attention (double-buffered KV, pass-reordered MMAs) --------------
#define APAD_B 144
#define ATS 9216
#define ATT_SMEM (2 * ATS + 2 * 4 * ATS)   // 92160

__device__ __forceinline__ void att_kvload(
    uint32_t sb, int s, int kt, size_t hoff, int tid,
    const __nv_bfloat16* __restrict__ kh_g, const __nv_bfloat16* __restrict__ kl_g,
    const __nv_bfloat16* __restrict__ vth_g, const __nv_bfloat16* __restrict__ vtl_g)
{
    uint32_t st = sb + 2 * ATS + s * 4 * ATS;
#pragma unroll
    for (int i = 0; i < 16; i++) {
        int u = tid + i * 128;
        int t = u >> 9, row = (u >> 3) & 63, c = u & 7;
        const __nv_bfloat16* src;
        if (t == 0)      src = kh_g + hoff + (size_t)(kt * 64 + row) * 64 + c * 8;
        else if (t == 1) src = kl_g + hoff + (size_t)(kt * 64 + row) * 64 + c * 8;
        else if (t == 2) src = vth_g + hoff + (size_t)row * T_ + kt * 64 + c * 8;
        else             src = vtl_g + hoff + (size_t)row * T_ + kt * 64 + c * 8;
        uint32_t dst = st + t * ATS + row * APAD_B + c * 16;
        asm volatile("cp.async.cg.shared.global [%0], [%1], 16;" :: "r"(dst), "l"(src));
    }
}

__global__ __launch_bounds__(128) void attn_mma(
    const __nv_bfloat16* __restrict__ qh_g, const __nv_bfloat16* __restrict__ ql_g,
    const __nv_bfloat16* __restrict__ kh_g, const __nv_bfloat16* __restrict__ kl_g,
    const __nv_bfloat16* __restrict__ vth_g, const __nv_bfloat16* __restrict__ vtl_g,
    __nv_bfloat16* __restrict__ aoh, __nv_bfloat16* __restrict__ aol,
    float* __restrict__ gepart)
{
    extern __shared__ char smr[];
    __shared__ float red[128];
    const int qt = (int)(gridDim.x - 1) - (int)blockIdx.x;   // heavy tiles first
    const int bh = blockIdx.y, q0 = qt * 64;
    const int tid = threadIdx.x, lane = tid & 31, w = tid >> 5;
    const int gID = lane >> 2, tg = lane & 3;
    uint32_t sb = (uint32_t)__cvta_generic_to_shared(smr);
    const size_t hoff = (size_t)bh * (T_ * 64);

#pragma unroll
    for (int i = 0; i < 8; i++) {
        int u = tid + i * 128;
        int t = u >> 9, row = (u >> 3) & 63, c = u & 7;
        const __nv_bfloat16* src = (t ? ql_g : qh_g) + hoff + (size_t)(q0 + row) * 64 + c * 8;
        uint32_t dst = sb + t * ATS + row * APAD_B + c * 16;
        asm volatile("cp.async.cg.shared.global [%0], [%1], 16;" :: "r"(dst), "l"(src));
    }
    att_kvload(sb, 0, 0, hoff, tid, kh_g, kl_g, vth_g, vtl_g);
    asm volatile("cp.async.commit_group;" ::: "memory");
    asm volatile("cp.async.wait_group 0;" ::: "memory");
    __syncthreads();

    float oacc[8][4];
#pragma unroll
    for (int nt = 0; nt < 8; nt++)
#pragma unroll
        for (int r = 0; r < 4; r++) oacc[nt][r] = 0.f;
    float mrow[2] = {-1e30f, -1e30f}, lrow[2] = {0.f, 0.f}, erow[2] = {0.f, 0.f};

    for (int kt = 0; kt <= qt; kt++) {
        if (kt < qt) {
            att_kvload(sb, (kt + 1) & 1, kt + 1, hoff, tid, kh_g, kl_g, vth_g, vtl_g);
            asm volatile("cp.async.commit_group;" ::: "memory");
        }
        uint32_t st = sb + 2 * ATS + (kt & 1) * 4 * ATS;

        float sacc[8][4];
#pragma unroll
        for (int nt = 0; nt < 8; nt++)
#pragma unroll
            for (int r = 0; r < 4; r++) sacc[nt][r] = 0.f;

#pragma unroll
        for (int ks = 0; ks < 4; ks++) {
            uint32_t aoff = sb + (w * 16 + gID) * APAD_B + (ks * 16 + tg * 2) * 2;
            uint32_t qh0 = *(const uint32_t*)(smr + (aoff - sb));
            uint32_t qh2 = *(const uint32_t*)(smr + (aoff - sb) + 16);
            uint32_t qh1 = *(const uint32_t*)(smr + (aoff - sb) + 8 * APAD_B);
            uint32_t qh3 = *(const uint32_t*)(smr + (aoff - sb) + 8 * APAD_B + 16);
            uint32_t ql0 = *(const uint32_t*)(smr + (aoff - sb) + ATS);
            uint32_t ql2 = *(const uint32_t*)(smr + (aoff - sb) + ATS + 16);
            uint32_t ql1 = *(const uint32_t*)(smr + (aoff - sb) + ATS + 8 * APAD_B);
            uint32_t ql3 = *(const uint32_t*)(smr + (aoff - sb) + ATS + 8 * APAD_B + 16);

            uint32_t kf[8][2];
            // pass 1 & 2: hi-K fragments
#pragma unroll
            for (int nt = 0; nt < 8; nt++) {
                uint32_t bo = (st - sb) + (nt * 8 + gID) * APAD_B + (ks * 16 + tg * 2) * 2;
                kf[nt][0] = *(const uint32_t*)(smr + bo);
                kf[nt][1] = *(const uint32_t*)(smr + bo + 16);
            }
#pragma unroll
            for (int nt = 0; nt < 8; nt++)
                mma16816(sacc[nt], qh0, qh1, qh2, qh3, kf[nt][0], kf[nt][1]);
#pragma unroll
            for (int nt = 0; nt < 8; nt++)
                mma16816(sacc[nt], ql0, ql1, ql2, ql3, kf[nt][0], kf[nt][1]);
            // pass 3: lo-K fragments (reuse registers)
#pragma unroll
            for (int nt = 0; nt < 8; nt++) {
                uint32_t bo = (st - sb) + ATS + (nt * 8 + gID) * APAD_B + (ks * 16 + tg * 2) * 2;
                kf[nt][0] = *(const uint32_t*)(smr + bo);
                kf[nt][1] = *(const uint32_t*)(smr + bo + 16);
            }
#pragma unroll
            for (int nt = 0; nt < 8; nt++)
                mma16816(sacc[nt], qh0, qh1, qh2, qh3, kf[nt][0], kf[nt][1]);
        }

        if (kt == qt) {
            int r0 = w * 16 + gID, r1 = r0 + 8;
#pragma unroll
            for (int nt = 0; nt < 8; nt++) {
                int c0 = nt * 8 + tg * 2, c1 = c0 + 1;
                if (c0 > r0) sacc[nt][0] = -1e30f;
                if (c1 > r0) sacc[nt][1] = -1e30f;
                if (c0 > r1) sacc[nt][2] = -1e30f;
                if (c1 > r1) sacc[nt][3] = -1e30f;
            }
        }

#pragma unroll
        for (int r = 0; r < 2; r++) {
            float tm = -1e30f;
#pragma unroll
            for (int nt = 0; nt < 8; nt++)
                tm = fmaxf(tm, fmaxf(sacc[nt][2 * r], sacc[nt][2 * r + 1]));
            tm = fmaxf(tm, __shfl_xor_sync(0xffffffffu, tm, 1));
            tm = fmaxf(tm, __shfl_xor_sync(0xffffffffu, tm, 2));
            float mn = fmaxf(mrow[r], tm);
            float sc = fast_exp(mrow[r] - mn);
            mrow[r] = mn;
            float se = 0.f, s2 = 0.f;
#pragma unroll
            for (int nt = 0; nt < 8; nt++) {
                float p0 = fast_exp(sacc[nt][2 * r] - mn);
                float p1 = fast_exp(sacc[nt][2 * r + 1] - mn);
                sacc[nt][2 * r] = p0; sacc[nt][2 * r + 1] = p1;
                se += p0 + p1;
                s2 += p0 * p0 + p1 * p1;
            }
            se += __shfl_xor_sync(0xffffffffu, se, 1);
            se += __shfl_xor_sync(0xffffffffu, se, 2);
            s2 += __shfl_xor_sync(0xffffffffu, s2, 1);
            s2 += __shfl_xor_sync(0xffffffffu, s2, 2);
            lrow[r] = lrow[r] * sc + se;
            erow[r] = erow[r] * sc * sc + s2;
#pragma unroll
            for (int nt = 0; nt < 8; nt++) {
                oacc[nt][2 * r] *= sc;
                oacc[nt][2 * r + 1] *= sc;
            }
        }

        // PV (pass-reordered)
#pragma unroll
        for (int ks = 0; ks < 4; ks++) {
            float* pa = sacc[2 * ks];
            float* pb = sacc[2 * ks + 1];
            uint32_t ph[4], pl[4];
            float hx, hy;
            ph[0] = pack_bf16x2(pa[0], pa[1]);
            hx = __bfloat162float(__float2bfloat16(pa[0]));
            hy = __bfloat162float(__float2bfloat16(pa[1]));
            pl[0] = pack_bf16x2(pa[0] - hx, pa[1] - hy);
            ph[1] = pack_bf16x2(pa[2], pa[3]);
            hx = __bfloat162float(__float2bfloat16(pa[2]));
            hy = __bfloat162float(__float2bfloat16(pa[3]));
            pl[1] = pack_bf16x2(pa[2] - hx, pa[3] - hy);
            ph[2] = pack_bf16x2(pb[0], pb[1]);
            hx = __bfloat162float(__float2bfloat16(pb[0]));
            hy = __bfloat162float(__float2bfloat16(pb[1]));
            pl[2] = pack_bf16x2(pb[0] - hx, pb[1] - hy);
            ph[3] = pack_bf16x2(pb[2], pb[3]);
            hx = __bfloat162float(__float2bfloat16(pb[2]));
            hy = __bfloat162float(__float2bfloat16(pb[3]));
            pl[3] = pack_bf16x2(pb[2] - hx, pb[3] - hy);

            uint32_t vf[8][2];
            // pass 1 & 2: hi-V fragments
#pragma unroll
            for (int nt = 0; nt < 8; nt++) {
                uint32_t bo = (st - sb) + 2 * ATS + (nt * 8 + gID) * APAD_B + (ks * 16 + tg * 2) * 2;
                vf[nt][0] = *(const uint32_t*)(smr + bo);
                vf[nt][1] = *(const uint32_t*)(smr + bo + 16);
            }
#pragma unroll
            for (int nt = 0; nt < 8; nt++)
                mma16816(oacc[nt], ph[0], ph[1], ph[2], ph[3], vf[nt][0], vf[nt][1]);
#pragma unroll
            for (int nt = 0; nt < 8; nt++)
                mma16816(oacc[nt], pl[0], pl[1], pl[2], pl[3], vf[nt][0], vf[nt][1]);
            // pass 3: lo-V fragments (reuse registers)
#pragma unroll
            for (int nt = 0; nt < 8; nt++) {
                uint32_t bo = (st - sb) + 3 * ATS + (nt * 8 + gID) * APAD_B + (ks * 16 + tg * 2) * 2;
                vf[nt][0] = *(const uint32_t*)(smr + bo);
                vf[nt][1] = *(const uint32_t*)(smr + bo + 16);
            }
#pragma unroll
            for (int nt = 0; nt < 8; nt++)
                mma16816(oacc[nt], ph[0], ph[1], ph[2], ph[3], vf[nt][0], vf[nt][1]);
        }

        asm volatile("cp.async.wait_group 0;" ::: "memory");
        __syncthreads();
    }

    // epilogue: write bf16 hi/lo of out (unmasked; mask handled by O-GEMM chunk skip)
    float linv0 = 1.f / lrow[0], linv1 = 1.f / lrow[1];
    int r0 = w * 16 + gID, r1 = r0 + 8;
    int b = bh >> 4, h = bh & 15;
    size_t base0 = (size_t)(b * T_ + q0 + r0) * C_ + h * DH_;
    size_t base1 = (size_t)(b * T_ + q0 + r1) * C_ + h * DH_;
#pragma unroll
    for (int nt = 0; nt < 8; nt++) {
        int col = nt * 8 + tg * 2;
        float v0 = oacc[nt][0] * linv0, v1 = oacc[nt][1] * linv0;
        float v2 = oacc[nt][2] * linv1, v3 = oacc[nt][3] * linv1;
        ushort2 H0, L0, H1, L1;
        bf16split(v0, H0.x, L0.x); bf16split(v1, H0.y, L0.y);
        bf16split(v2, H1.x, L1.x); bf16split(v3, H1.y, L1.y);
        *(ushort2*)&aoh[base0 + col] = H0;
        *(ushort2*)&aol[base0 + col] = L0;
        *(ushort2*)&aoh[base1 + col] = H1;
        *(ushort2*)&aol[base1 + col] = L1;
    }

    red[tid] = (tg == 0) ? (erow[0] * linv0 * linv0 + erow[1] * linv1 * linv1) : 0.f;
    __syncthreads();
    for (int o = 64; o > 0; o >>= 1) {
        if (tid < o) red[tid] += red[tid + o];
        __syncthreads();
    }
    if (tid == 0) gepart[bh * 16 + qt] = red[0];
}

// -------------- head energy -> entropy -> adaptive head mask --------------
__global__ void headmask(const float* __restrict__ epart, float* __restrict__ maskout)
{
    __shared__ double e[64];
    __shared__ double cand[64];
    int t = threadIdx.x;
    double s = 0.0;
    for (int i = 0; i < 16; i++) s += (double)epart[t * 16 + i];
    e[t] = s / 1048576.0;
    __syncthreads();
    int b = t >> 4;
    double m = -1e300;
    for (int j = 0; j < 16; j++) m = fmax(m, e[b * 16 + j]);
    double Z = 0.0;
    for (int j = 0; j < 16; j++) Z += exp(e[b * 16 + j] - m);
    double ent = 0.0;
    for (int j = 0; j < 16; j++) {
        double p = exp(e[b * 16 + j] - m) / Z;
        ent -= p * log(p + 1e-9);
    }
    double entn = fmin(fmax(ent / log(16.0), 0.0), 1.0);
    int keep = (int)rint(2.0 + entn * 4.0);
    double eh = e[t];
    int g = 0;
    for (int j = 0; j < 16; j++) g += (e[b * 16 + j] > eh);
    cand[t] = (g <= keep - 1) ? eh : 1e300;
    __syncthreads();
    double th = 1e300;
    for (int j = 0; j < 16; j++) th = fmin(th, cand[b * 16 + j]);
    maskout[t] = (eh >= th) ? 1.f : 0.f;
}

// ---------------- launch ----------------
extern "C" void kernel_launch(void* const* d_in, const int* in_sizes, int n_in,
                              void* d_out, int out_size)
{
    const float* x  = (const float*)d_in[0];
    const float* qw = (const float*)d_in[1];
    const float* qb = (const float*)d_in[2];
    const float* kw = (const float*)d_in[3];
    const float* kb = (const float*)d_in[4];
    const float* vw = (const float*)d_in[5];
    const float* vb = (const float*)d_in[6];
    const float* ow = (const float*)d_in[7];
    const float* ob = (const float*)d_in[8];
    float* out = (float*)d_out;

    float *gq, *gep, *gm;
    cudaGetSymbolAddress((void**)&gq, g_q);
    cudaGetSymbolAddress((void**)&gep, g_epart);
    cudaGetSymbolAddress((void**)&gm, g_mask);

    __nv_bfloat16 *xh, *xl, *x3, *qws, *kwh, *kwl, *vwh, *vwl, *owh, *owl, *aoh, *aol;
    __nv_bfloat16 *qsh, *qsl, *ksh, *ksl, *vth, *vtl;
    cudaGetSymbolAddress((void**)&xh, g_xh);   cudaGetSymbolAddress((void**)&xl, g_xl);
    cudaGetSymbolAddress((void**)&x3, g_x3);   cudaGetSymbolAddress((void**)&qws, g_qws);
    cudaGetSymbolAddress((void**)&kwh, g_kwh); cudaGetSymbolAddress((void**)&kwl, g_kwl);
    cudaGetSymbolAddress((void**)&vwh, g_vwh); cudaGetSymbolAddress((void**)&vwl, g_vwl);
    cudaGetSymbolAddress((void**)&owh, g_owh); cudaGetSymbolAddress((void**)&owl, g_owl);
    cudaGetSymbolAddress((void**)&aoh, g_aoh); cudaGetSymbolAddress((void**)&aol, g_aol);
    cudaGetSymbolAddress((void**)&qsh, g_qsh); cudaGetSymbolAddress((void**)&qsl, g_qsl);
    cudaGetSymbolAddress((void**)&ksh, g_ksh); cudaGetSymbolAddress((void**)&ksl, g_ksl);
    cudaGetSymbolAddress((void**)&vth, g_vth); cudaGetSymbolAddress((void**)&vtl, g_vtl);

    cudaFuncSetAttribute((const void*)proj_fused,
                         cudaFuncAttributeMaxDynamicSharedMemorySize, 2 * STAGE_B);
    cudaFuncSetAttribute((const void*)gemm_o,
                         cudaFuncAttributeMaxDynamicSharedMemorySize, 2 * STAGE_B);
    cudaFuncSetAttribute((const void*)attn_mma,
                         cudaFuncAttributeMaxDynamicSharedMemorySize, ATT_SMEM);

    // fused prep: x 3-split + all weight preps (one launch)
    prep_fused<<<M_ * C_ / 1024 + 4 * (C_ * C_ / 1024), 256>>>(
        (const float4*)x, (const float4*)kw, (const float4*)vw,
        (const float4*)ow, (const float4*)qw,
        (ushort4*)xh, (ushort4*)xl, (ushort4*)x3,
        (ushort4*)kwh, (ushort4*)kwl, (ushort4*)vwh, (ushort4*)vwl,
        (ushort4*)owh, (ushort4*)owl, (ushort4*)qws);

    // fused projections: K (256) + V (256) + Q (512) CTAs in one launch
    proj_fused<<<1024, 256, 2 * STAGE_B>>>(
        xh, xl, x3, qws, kwh, kwl, vwh, vwl,
        qb, kb, vb, gq, ksh, ksl, vth, vtl);

    qpost<<<BH_ * T_ / 4, 256>>>(gq, qsh, qsl);

    attn_mma<<<dim3(16, BH_), 128, ATT_SMEM>>>(qsh, qsl, ksh, ksl, vth, vtl, aoh, aol, gep);
    headmask<<<1, 64>>>(gep, gm);

    dim3 tGrid(C_ / 128, M_ / 128);
    gemm_o<<<tGrid, 256, 2 * STAGE_B>>>(aoh, aol, owh, owl, ob, out, gm);
}

// round 17
// speedup vs baseline: 1.0723x; 1.0723x over previous
#include <cuda_runtime.h>
#include <cuda_bf16.h>
#include <cuda_fp16.h>
#include <math.h>
#include <stdint.h>

#define B_  4
#define T_  1024
#define C_  1024
#define H_  16
#define DH_ 64
#define BH_ 64            // B_*H_
#define M_  4096          // B_*T_

// ---------------- scratch (device globals: allocation-free) ----------------
__device__ float g_q[BH_ * T_ * DH_];       // fp32 q after projection
__device__ float g_epart[BH_ * 16];
__device__ float g_mask[BH_];

// bf16 split buffers (some reused as fp16 bit-storage)
__device__ __nv_bfloat16 g_xh[M_ * C_],  g_xl[M_ * C_], g_x3[M_ * C_];
__device__ unsigned short g_xf[M_ * C_];                   // fp16 x (single)
__device__ __nv_bfloat16 g_qws[C_ * C_];
__device__ __nv_bfloat16 g_kwh[C_ * C_], g_kwl[C_ * C_];
__device__ __nv_bfloat16 g_vwh[C_ * C_], g_vwl[C_ * C_];   // holds fp16 bits now
__device__ __nv_bfloat16 g_owh[C_ * C_], g_owl[C_ * C_];
__device__ __nv_bfloat16 g_aoh[M_ * C_], g_aol[M_ * C_];
// attention operand splits
__device__ __nv_bfloat16 g_qsh[BH_ * T_ * DH_], g_qsl[BH_ * T_ * DH_];   // (bh,t,d) bf16
__device__ __nv_bfloat16 g_ksh[BH_ * T_ * DH_], g_ksl[BH_ * T_ * DH_];   // (bh,t,d) bf16
__device__ __nv_bfloat16 g_vth[BH_ * T_ * DH_], g_vtl[BH_ * T_ * DH_];   // (bh,d,t) fp16 bits

__constant__ int KEEPC[16] = {22,21,20,19,18,18,17,16,15,14,13,13,12,11,10,9};

// ---------------- helpers ----------------
__device__ __forceinline__ void twosum(float& s, float& c, float v) {
    float t  = __fadd_rn(s, v);
    float bo = __fsub_rn(t, s);
    float e1 = __fsub_rn(s, __fsub_rn(t, bo));
    float e2 = __fsub_rn(v, bo);
    c = __fadd_rn(c, __fadd_rn(e1, e2));
    s = t;
}

// fast exp (no MUFU): d <= 0, rel err ~2.4e-8
__device__ __forceinline__ float fast_exp(float d) {
    d = fmaxf(d, -80.f);
    float t = d * 1.4426950408889634f;
    float n = rintf(t);
    float f = fmaf(n, -0.693147182464599609375f, d);
    f = fmaf(n, 1.9046542999577680452e-9f, f);
    float p = 1.3888888888888889e-3f;
    p = fmaf(p, f, 8.3333333333333332e-3f);
    p = fmaf(p, f, 4.1666666666666664e-2f);
    p = fmaf(p, f, 1.6666666666666666e-1f);
    p = fmaf(p, f, 0.5f);
    p = fmaf(p, f, 1.0f);
    p = fmaf(p, f, 1.0f);
    int j = (int)n;
    return p * __uint_as_float((unsigned)(127 + j) << 23);
}

__device__ __forceinline__ uint32_t pack_f16x2(float lo, float hi) {
    uint32_t r;
    asm("cvt.rn.f16x2.f32 %0, %1, %2;" : "=r"(r) : "f"(hi), "f"(lo));
    return r;
}

__device__ __forceinline__ void mma16816(float* d,
    uint32_t a0, uint32_t a1, uint32_t a2, uint32_t a3,
    uint32_t b0, uint32_t b1)
{
    asm volatile(
        "mma.sync.aligned.m16n8k16.row.col.f32.bf16.bf16.f32 "
        "{%0,%1,%2,%3}, {%4,%5,%6,%7}, {%8,%9}, {%0,%1,%2,%3};"
        : "+f"(d[0]), "+f"(d[1]), "+f"(d[2]), "+f"(d[3])
        : "r"(a0), "r"(a1), "r"(a2), "r"(a3), "r"(b0), "r"(b1));
}

__device__ __forceinline__ void mma16816h(float* d,
    uint32_t a0, uint32_t a1, uint32_t a2, uint32_t a3,
    uint32_t b0, uint32_t b1)
{
    asm volatile(
        "mma.sync.aligned.m16n8k16.row.col.f32.f16.f16.f32 "
        "{%0,%1,%2,%3}, {%4,%5,%6,%7}, {%8,%9}, {%0,%1,%2,%3};"
        : "+f"(d[0]), "+f"(d[1]), "+f"(d[2]), "+f"(d[3])
        : "r"(a0), "r"(a1), "r"(a2), "r"(a3), "r"(b0), "r"(b1));
}

__device__ __forceinline__ void ldsm4(uint32_t addr,
    uint32_t& r0, uint32_t& r1, uint32_t& r2, uint32_t& r3)
{
    asm volatile("ldmatrix.sync.aligned.m8n8.x4.shared.b16 {%0,%1,%2,%3}, [%4];"
                 : "=r"(r0), "=r"(r1), "=r"(r2), "=r"(r3) : "r"(addr));
}

__device__ __forceinline__ void bf16split(float x, unsigned short& h, unsigned short& l) {
    __nv_bfloat16 hh = __float2bfloat16(x);
    h = __bfloat16_as_ushort(hh);
    l = __bfloat16_as_ushort(__float2bfloat16(x - __bfloat162float(hh)));
}

__device__ __forceinline__ void f16split(float x, unsigned short& h, unsigned short& l) {
    __half hh = __float2half_rn(x);
    h = __half_as_ushort(hh);
    l = __half_as_ushort(__float2half_rn(x - __half2float(hh)));
}

// ---------------- fused prep ----------------
__global__ void prep_fused(const float4* __restrict__ x,
                           const float4* __restrict__ kw, const float4* __restrict__ vw,
                           const float4* __restrict__ ow, const float4* __restrict__ qw,
                           ushort4* __restrict__ xh, ushort4* __restrict__ xl,
                           ushort4* __restrict__ x3, ushort4* __restrict__ xf,
                           ushort4* __restrict__ kwh, ushort4* __restrict__ kwl,
                           ushort4* __restrict__ vwh, ushort4* __restrict__ vwl,
                           ushort4* __restrict__ owh, ushort4* __restrict__ owl,
                           ushort4* __restrict__ qws)
{
    int bid = blockIdx.x;
    if (bid < M_ * C_ / 1024) {                       // x: 3-term bf16 split + fp16 single
        int i = bid * 256 + threadIdx.x;
        float4 v = x[i];
        float a[4] = {v.x, v.y, v.z, v.w};
        ushort4 H, L, T3, F;
        unsigned short* hp = &H.x; unsigned short* lp = &L.x;
        unsigned short* tp = &T3.x; unsigned short* fp = &F.x;
#pragma unroll
        for (int j = 0; j < 4; j++) {
            __nv_bfloat16 h = __float2bfloat16(a[j]);
            float r1 = a[j] - __bfloat162float(h);
            __nv_bfloat16 l = __float2bfloat16(r1);
            float r2 = r1 - __bfloat162float(l);
            tp[j] = __bfloat16_as_ushort(__float2bfloat16(r2));
            hp[j] = __bfloat16_as_ushort(h);
            lp[j] = __bfloat16_as_ushort(l);
            fp[j] = __half_as_ushort(__float2half_rn(a[j]));
        }
        xh[i] = H; xl[i] = L; x3[i] = T3; xf[i] = F;
        return;
    }
    int u = bid - M_ * C_ / 1024;                     // 0..4095
    int which = u >> 10;                              // 0 kw(bf16), 1 vw(fp16), 2 ow(bf16), 3 qw-sign
    int i = (u & 1023) * 256 + threadIdx.x;
    if (which == 3) {
        float4 v = qw[i];
        ushort4 o;
        o.x = (v.x > 0.f) ? 0x3F80 : ((v.x < 0.f) ? 0xBF80 : 0);
        o.y = (v.y > 0.f) ? 0x3F80 : ((v.y < 0.f) ? 0xBF80 : 0);
        o.z = (v.z > 0.f) ? 0x3F80 : ((v.z < 0.f) ? 0xBF80 : 0);
        o.w = (v.w > 0.f) ? 0x3F80 : ((v.w < 0.f) ? 0xBF80 : 0);
        qws[i] = o;
        return;
    }
    const float4* src = (which == 0) ? kw : (which == 1) ? vw : ow;
    ushort4* hi = (which == 0) ? kwh : (which == 1) ? vwh : owh;
    ushort4* lo = (which == 0) ? kwl : (which == 1) ? vwl : owl;
    float4 v = src[i];
    float a[4] = {v.x, v.y, v.z, v.w};
    ushort4 H, L;
    unsigned short* hp = &H.x; unsigned short* lp = &L.x;
    if (which == 1) {
#pragma unroll
        for (int j = 0; j < 4; j++) f16split(a[j], hp[j], lp[j]);
    } else {
#pragma unroll
        for (int j = 0; j < 4; j++) bf16split(a[j], hp[j], lp[j]);
    }
    hi[i] = H; lo[i] = L;
}

// ---------------- shared GEMM mainloop (K / O paths, bf16 3-MMA) ----------------
#define TILE_B   10240
#define STAGE_B  40960
#define NCHUNK   32

__device__ __forceinline__ void load_chunk_async(
    uint32_t sbase,
    const __nv_bfloat16* __restrict__ Ahi, const __nv_bfloat16* __restrict__ Alo,
    const __nv_bfloat16* __restrict__ Bhi, const __nv_bfloat16* __restrict__ Blo,
    int m0, int n0, int k0, int tid)
{
#pragma unroll
    for (int i = 0; i < 8; i++) {
        int u = tid + i * 256;
        int tile = u >> 9;
        int idx = u & 511;
        int row = idx >> 2;
        int jj = idx & 3;
        const __nv_bfloat16* g;
        if (tile == 0)      g = Ahi + (size_t)(m0 + row) * C_ + k0 + jj * 8;
        else if (tile == 1) g = Alo + (size_t)(m0 + row) * C_ + k0 + jj * 8;
        else if (tile == 2) g = Bhi + (size_t)(n0 + row) * C_ + k0 + jj * 8;
        else                g = Blo + (size_t)(n0 + row) * C_ + k0 + jj * 8;
        uint32_t dst = sbase + tile * TILE_B + row * 80 + jj * 16;
        asm volatile("cp.async.cg.shared.global [%0], [%1], 16;" :: "r"(dst), "l"(g));
    }
}

#define GEMM_MAINLOOP(ACT_EXPR, NA)                                                   \
    const uint32_t aBase = (uint32_t)((wm * 64 + (lane & 7) + ((lane >> 3) & 1) * 8) * 80 \
                                      + ((lane >> 4) & 1) * 16);                      \
    const uint32_t bBase = (uint32_t)((wn * 32 + (lane & 7) + ((lane >> 4) & 1) * 8) * 80 \
                                      + ((lane >> 3) & 1) * 16);                      \
    load_chunk_async(sbase, Ahi, Alo, Bhi, Blo, m0, n0, (ACT_EXPR(0)) * 32, tid);     \
    asm volatile("cp.async.commit_group;" ::: "memory");                              \
    asm volatile("cp.async.wait_group 0;" ::: "memory");                              \
    __syncthreads();                                                                  \
    for (int c = 0; c < (NA); c++) {                                                  \
        if (c + 1 < (NA)) {                                                           \
            load_chunk_async(sbase + ((c + 1) & 1) * STAGE_B,                         \
                             Ahi, Alo, Bhi, Blo, m0, n0, (ACT_EXPR(c + 1)) * 32, tid);\
            asm volatile("cp.async.commit_group;" ::: "memory");                      \
        }                                                                             \
        const uint32_t stw = sbase + (c & 1) * STAGE_B;                               \
        _Pragma("unroll")                                                             \
        for (int ks = 0; ks < 2; ks++) {                                              \
            const uint32_t kb = ks * 32;                                              \
            uint32_t ah[4][4], al[4][4], bhf[4][2], blf[4][2];                        \
            ldsm4(stw + 2 * TILE_B + bBase + kb,                                      \
                  bhf[0][0], bhf[0][1], bhf[1][0], bhf[1][1]);                        \
            ldsm4(stw + 2 * TILE_B + 1280 + bBase + kb,                               \
                  bhf[2][0], bhf[2][1], bhf[3][0], bhf[3][1]);                        \
            ldsm4(stw + 3 * TILE_B + bBase + kb,                                      \
                  blf[0][0], blf[0][1], blf[1][0], blf[1][1]);                        \
            ldsm4(stw + 3 * TILE_B + 1280 + bBase + kb,                               \
                  blf[2][0], blf[2][1], blf[3][0], blf[3][1]);                        \
            _Pragma("unroll")                                                         \
            for (int mt = 0; mt < 4; mt++) {                                          \
                ldsm4(stw + aBase + mt * 1280 + kb,                                   \
                      ah[mt][0], ah[mt][1], ah[mt][2], ah[mt][3]);                    \
                ldsm4(stw + TILE_B + aBase + mt * 1280 + kb,                          \
                      al[mt][0], al[mt][1], al[mt][2], al[mt][3]);                    \
            }                                                                         \
            _Pragma("unroll")                                                         \
            for (int mt = 0; mt < 4; mt++)                                            \
                _Pragma("unroll")                                                     \
                for (int nt = 0; nt < 4; nt++)                                        \
                    mma16816(acc[mt][nt], ah[mt][0], ah[mt][1], ah[mt][2], ah[mt][3], \
                             bhf[nt][0], bhf[nt][1]);                                 \
            _Pragma("unroll")                                                         \
            for (int mt = 0; mt < 4; mt++)                                            \
                _Pragma("unroll")                                                     \
                for (int nt = 0; nt < 4; nt++)                                        \
                    mma16816(acc[mt][nt], al[mt][0], al[mt][1], al[mt][2], al[mt][3], \
                             bhf[nt][0], bhf[nt][1]);                                 \
            _Pragma("unroll")                                                         \
            for (int mt = 0; mt < 4; mt++)                                            \
                _Pragma("unroll")                                                     \
                for (int nt = 0; nt < 4; nt++)                                        \
                    mma16816(acc[mt][nt], ah[mt][0], ah[mt][1], ah[mt][2], ah[mt][3], \
                             blf[nt][0], blf[nt][1]);                                 \
        }                                                                             \
        if (c + 1 < (NA))                                                             \
            asm volatile("cp.async.wait_group 0;" ::: "memory");                      \
        __syncthreads();                                                              \
    }

#define ACT_ID(c) (c)
#define ACT_LUT(c) (act[c])

// V path loader: A = xf single fp16, B = vwh/vwl fp16
#define VSTG_B 30720
__device__ __forceinline__ void vload_chunk_async(
    uint32_t sbase, const __nv_bfloat16* __restrict__ xf,
    const __nv_bfloat16* __restrict__ Bhi, const __nv_bfloat16* __restrict__ Blo,
    int m0, int n0, int k0, int tid)
{
#pragma unroll
    for (int i = 0; i < 6; i++) {
        int u = tid + i * 256;               // 0..1535
        const __nv_bfloat16* g;
        uint32_t dst;
        if (u < 512) {
            int row = u >> 2, jj = u & 3;
            g = xf + (size_t)(m0 + row) * C_ + k0 + jj * 8;
            dst = sbase + row * 80 + jj * 16;
        } else {
            int v = u - 512;
            int sub = v >> 9;
            int idx = v & 511;
            int row = idx >> 2, jj = idx & 3;
            g = (sub ? Blo : Bhi) + (size_t)(n0 + row) * C_ + k0 + jj * 8;
            dst = sbase + TILE_B + sub * TILE_B + row * 80 + jj * 16;
        }
        asm volatile("cp.async.cg.shared.global [%0], [%1], 16;" :: "r"(dst), "l"(g));
    }
}

#define QTILE_B  5120
#define QSTAGE_B 25600
#define QNCH     32

__device__ __forceinline__ void qload_chunk_async(
    uint32_t sbase,
    const __nv_bfloat16* __restrict__ X1, const __nv_bfloat16* __restrict__ X2,
    const __nv_bfloat16* __restrict__ X3, const __nv_bfloat16* __restrict__ Ws,
    int m0, int n0, int k0, int tid)
{
#pragma unroll
    for (int i = 0; i < 5; i++) {
        int u = tid + i * 256;
        const __nv_bfloat16* g;
        uint32_t dst;
        if (u < 768) {
            int term = u >> 8;
            int idx = u & 255;
            int row = idx >> 2, jj = idx & 3;
            const __nv_bfloat16* base = (term == 0) ? X1 : (term == 1) ? X2 : X3;
            g = base + (size_t)(m0 + row) * C_ + k0 + jj * 8;
            dst = sbase + term * QTILE_B + row * 80 + jj * 16;
        } else {
            int v = u - 768;
            int row = v >> 2, jj = v & 3;
            g = Ws + (size_t)(n0 + row) * C_ + k0 + jj * 8;
            dst = sbase + 3 * QTILE_B + row * 80 + jj * 16;
        }
        asm volatile("cp.async.cg.shared.global [%0], [%1], 16;" :: "r"(dst), "l"(g));
    }
}

// ---------------- fused projection kernel: K (0-255) | V (256-511) | Q (512-1023) ----------------
__global__ __launch_bounds__(256) void proj_fused(
    const __nv_bfloat16* __restrict__ xh, const __nv_bfloat16* __restrict__ xl,
    const __nv_bfloat16* __restrict__ x3, const __nv_bfloat16* __restrict__ xf,
    const __nv_bfloat16* __restrict__ qws,
    const __nv_bfloat16* __restrict__ kwh, const __nv_bfloat16* __restrict__ kwl,
    const __nv_bfloat16* __restrict__ vwh, const __nv_bfloat16* __restrict__ vwl,
    const float* __restrict__ qb, const float* __restrict__ kb, const float* __restrict__ vb,
    float* __restrict__ Q,
    __nv_bfloat16* __restrict__ kh, __nv_bfloat16* __restrict__ kl,
    __nv_bfloat16* __restrict__ vth, __nv_bfloat16* __restrict__ vtl)
{
    extern __shared__ char smc[];
    const int tid = threadIdx.x;
    const int lane = tid & 31, wid = tid >> 5;
    const int wm = wid >> 2, wn = wid & 3;
    const int gID = lane >> 2, tg = lane & 3;
    uint32_t sbase = (uint32_t)__cvta_generic_to_shared(smc);
    const int bid = blockIdx.x;

    if (bid < 256) {
        // ---------------- K path (bf16 3-MMA) ----------------
        const int lb = bid;
        const int m0 = (lb >> 3) * 128, n0 = (lb & 7) * 128;
        const __nv_bfloat16* Ahi = xh;
        const __nv_bfloat16* Alo = xl;
        const __nv_bfloat16* Bhi = kwh;
        const __nv_bfloat16* Blo = kwl;
        const float* bias = kb;

        float acc[4][4][4];
#pragma unroll
        for (int mt = 0; mt < 4; mt++)
#pragma unroll
            for (int nt = 0; nt < 4; nt++)
#pragma unroll
                for (int r = 0; r < 4; r++) acc[mt][nt][r] = 0.f;

        GEMM_MAINLOOP(ACT_ID, NCHUNK)

        // K epilogue: per-row RMS over each head, bf16 split-write
        float* tb = (float*)smc;     // [128][132]
#pragma unroll
        for (int mt = 0; mt < 4; mt++) {
            int ml = wm * 64 + mt * 16 + gID;
#pragma unroll
            for (int nt = 0; nt < 4; nt++) {
                int nl = wn * 32 + nt * 8 + tg * 2;
                float b0v = bias[n0 + nl], b1v = bias[n0 + nl + 1];
                tb[ml * 132 + nl]           = acc[mt][nt][0] + b0v;
                tb[ml * 132 + nl + 1]       = acc[mt][nt][1] + b1v;
                tb[(ml + 8) * 132 + nl]     = acc[mt][nt][2] + b0v;
                tb[(ml + 8) * 132 + nl + 1] = acc[mt][nt][3] + b1v;
            }
        }
        __syncthreads();
        {
            int ml = tid >> 1, h2 = tid & 1;
            const float* row = &tb[ml * 132 + h2 * 64];
            float ss = 0.f;
#pragma unroll
            for (int j4 = 0; j4 < 16; j4++) {
                float4 v = *(const float4*)&row[j4 * 4];
                ss += v.x * v.x + v.y * v.y + v.z * v.z + v.w * v.w;
            }
            float inv = 1.f / (sqrtf(ss * (1.f / 64.f)) + 1e-6f);
            int m = m0 + ml;
            int bb = m >> 10, t = m & 1023;
            int h = (n0 >> 6) + h2;
            __nv_bfloat16* oh = kh + (((size_t)(bb * H_ + h)) * T_ + t) * DH_;
            __nv_bfloat16* ol = kl + (((size_t)(bb * H_ + h)) * T_ + t) * DH_;
#pragma unroll
            for (int j4 = 0; j4 < 16; j4++) {
                float4 v = *(const float4*)&row[j4 * 4];
                ushort4 Hv, Lv;
                bf16split(v.x * inv, Hv.x, Lv.x);
                bf16split(v.y * inv, Hv.y, Lv.y);
                bf16split(v.z * inv, Hv.z, Lv.z);
                bf16split(v.w * inv, Hv.w, Lv.w);
                *(ushort4*)&oh[j4 * 4] = Hv;
                *(ushort4*)&ol[j4 * 4] = Lv;
            }
        }
    } else if (bid < 512) {
        // ---------------- V path (fp16 2-MMA: xf single x vw hi/lo) ----------------
        const int lb = bid & 255;
        const int m0 = (lb >> 3) * 128, n0 = (lb & 7) * 128;
        const uint32_t aBase = (uint32_t)((wm * 64 + (lane & 7) + ((lane >> 3) & 1) * 8) * 80
                                          + ((lane >> 4) & 1) * 16);
        const uint32_t bBase = (uint32_t)((wn * 32 + (lane & 7) + ((lane >> 4) & 1) * 8) * 80
                                          + ((lane >> 3) & 1) * 16);

        float acc[4][4][4];
#pragma unroll
        for (int mt = 0; mt < 4; mt++)
#pragma unroll
            for (int nt = 0; nt < 4; nt++)
#pragma unroll
                for (int r = 0; r < 4; r++) acc[mt][nt][r] = 0.f;

        vload_chunk_async(sbase, xf, vwh, vwl, m0, n0, 0, tid);
        asm volatile("cp.async.commit_group;" ::: "memory");
        asm volatile("cp.async.wait_group 0;" ::: "memory");
        __syncthreads();

        for (int c = 0; c < NCHUNK; c++) {
            if (c + 1 < NCHUNK) {
                vload_chunk_async(sbase + ((c + 1) & 1) * VSTG_B,
                                  xf, vwh, vwl, m0, n0, (c + 1) * 32, tid);
                asm volatile("cp.async.commit_group;" ::: "memory");
            }
            const uint32_t stw = sbase + (c & 1) * VSTG_B;
#pragma unroll
            for (int ks = 0; ks < 2; ks++) {
                const uint32_t kb = ks * 32;
                uint32_t ah[4][4], bhf[4][2], blf[4][2];
                ldsm4(stw + TILE_B + bBase + kb,
                      bhf[0][0], bhf[0][1], bhf[1][0], bhf[1][1]);
                ldsm4(stw + TILE_B + 1280 + bBase + kb,
                      bhf[2][0], bhf[2][1], bhf[3][0], bhf[3][1]);
                ldsm4(stw + 2 * TILE_B + bBase + kb,
                      blf[0][0], blf[0][1], blf[1][0], blf[1][1]);
                ldsm4(stw + 2 * TILE_B + 1280 + bBase + kb,
                      blf[2][0], blf[2][1], blf[3][0], blf[3][1]);
#pragma unroll
                for (int mt = 0; mt < 4; mt++)
                    ldsm4(stw + aBase + mt * 1280 + kb,
                          ah[mt][0], ah[mt][1], ah[mt][2], ah[mt][3]);
#pragma unroll
                for (int mt = 0; mt < 4; mt++)
#pragma unroll
                    for (int nt = 0; nt < 4; nt++)
                        mma16816h(acc[mt][nt], ah[mt][0], ah[mt][1], ah[mt][2], ah[mt][3],
                                  bhf[nt][0], bhf[nt][1]);
#pragma unroll
                for (int mt = 0; mt < 4; mt++)
#pragma unroll
                    for (int nt = 0; nt < 4; nt++)
                        mma16816h(acc[mt][nt], ah[mt][0], ah[mt][1], ah[mt][2], ah[mt][3],
                                  blf[nt][0], blf[nt][1]);
            }
            if (c + 1 < NCHUNK)
                asm volatile("cp.async.wait_group 0;" ::: "memory");
            __syncthreads();
        }

        // V epilogue: transposed tile, fp16 split-write (bh,d,t)
        float* tb = (float*)smc;     // [128][132] transposed
#pragma unroll
        for (int mt = 0; mt < 4; mt++) {
            int ml = wm * 64 + mt * 16 + gID;
#pragma unroll
            for (int nt = 0; nt < 4; nt++) {
                int nl = wn * 32 + nt * 8 + tg * 2;
                float b0v = vb[n0 + nl], b1v = vb[n0 + nl + 1];
                tb[nl * 132 + ml]           = acc[mt][nt][0] + b0v;
                tb[(nl + 1) * 132 + ml]     = acc[mt][nt][1] + b1v;
                tb[nl * 132 + ml + 8]       = acc[mt][nt][2] + b0v;
                tb[(nl + 1) * 132 + ml + 8] = acc[mt][nt][3] + b1v;
            }
        }
        __syncthreads();
        {
            int nl = tid >> 1, mhalf = (tid & 1) * 64;
            const float* row = &tb[nl * 132 + mhalf];
            int h = (n0 >> 6) + (nl >> 6);
            int d = nl & 63;
            int bb = m0 >> 10;
            int t0 = (m0 & 1023) + mhalf;
            __nv_bfloat16* oh = vth + (((size_t)(bb * H_ + h)) * DH_ + d) * T_ + t0;
            __nv_bfloat16* ol = vtl + (((size_t)(bb * H_ + h)) * DH_ + d) * T_ + t0;
#pragma unroll
            for (int j4 = 0; j4 < 16; j4++) {
                float4 v = *(const float4*)&row[j4 * 4];
                ushort4 Hv, Lv;
                f16split(v.x, Hv.x, Lv.x);
                f16split(v.y, Hv.y, Lv.y);
                f16split(v.z, Hv.z, Lv.z);
                f16split(v.w, Hv.w, Lv.w);
                *(ushort4*)&oh[j4 * 4] = Hv;
                *(ushort4*)&ol[j4 * 4] = Lv;
            }
        }
    } else {
        // ---------------- Q path (exact 3-term split + chunked TwoSum): 64x128 ----------------
        const int qid = bid - 512;                   // 0..511
        const int m0 = (qid >> 3) * 64, n0 = (qid & 7) * 128;

        const uint32_t aQBase = (uint32_t)((wm * 32 + (lane & 7) + ((lane >> 3) & 1) * 8) * 80
                                           + ((lane >> 4) & 1) * 16);
        const uint32_t bQBase = (uint32_t)((wn * 32 + (lane & 7) + ((lane >> 4) & 1) * 8) * 80
                                           + ((lane >> 3) & 1) * 16);

        float s_[2][4][4], c_[2][4][4];
#pragma unroll
        for (int mt = 0; mt < 2; mt++)
#pragma unroll
            for (int nt = 0; nt < 4; nt++)
#pragma unroll
                for (int r = 0; r < 4; r++) { s_[mt][nt][r] = 0.f; c_[mt][nt][r] = 0.f; }

        qload_chunk_async(sbase, xh, xl, x3, qws, m0, n0, 0, tid);
        asm volatile("cp.async.commit_group;" ::: "memory");
        asm volatile("cp.async.wait_group 0;" ::: "memory");
        __syncthreads();

        for (int c = 0; c < QNCH; c++) {
            if (c + 1 < QNCH) {
                qload_chunk_async(sbase + ((c + 1) & 1) * QSTAGE_B,
                                  xh, xl, x3, qws, m0, n0, (c + 1) * 32, tid);
                asm volatile("cp.async.commit_group;" ::: "memory");
            }
            const uint32_t stq = sbase + (c & 1) * QSTAGE_B;

            float tacc[2][4][4];
#pragma unroll
            for (int mt = 0; mt < 2; mt++)
#pragma unroll
                for (int nt = 0; nt < 4; nt++)
#pragma unroll
                    for (int r = 0; r < 4; r++) tacc[mt][nt][r] = 0.f;

#pragma unroll
            for (int ks = 0; ks < 2; ks++) {
                const uint32_t kb = ks * 32;
                uint32_t bw[4][2];
                ldsm4(stq + 3 * QTILE_B + bQBase + kb,
                      bw[0][0], bw[0][1], bw[1][0], bw[1][1]);
                ldsm4(stq + 3 * QTILE_B + 1280 + bQBase + kb,
                      bw[2][0], bw[2][1], bw[3][0], bw[3][1]);
#pragma unroll
                for (int term = 0; term < 3; term++) {
                    uint32_t ah[2][4];
#pragma unroll
                    for (int mt = 0; mt < 2; mt++)
                        ldsm4(stq + term * QTILE_B + aQBase + mt * 1280 + kb,
                              ah[mt][0], ah[mt][1], ah[mt][2], ah[mt][3]);
#pragma unroll
                    for (int mt = 0; mt < 2; mt++)
#pragma unroll
                        for (int nt = 0; nt < 4; nt++)
                            mma16816(tacc[mt][nt], ah[mt][0], ah[mt][1], ah[mt][2], ah[mt][3],
                                     bw[nt][0], bw[nt][1]);
                }
            }
#pragma unroll
            for (int mt = 0; mt < 2; mt++)
#pragma unroll
                for (int nt = 0; nt < 4; nt++)
#pragma unroll
                    for (int r = 0; r < 4; r++)
                        twosum(s_[mt][nt][r], c_[mt][nt][r], tacc[mt][nt][r]);

            if (c + 1 < QNCH)
                asm volatile("cp.async.wait_group 0;" ::: "memory");
            __syncthreads();
        }

#pragma unroll
        for (int mt = 0; mt < 2; mt++) {
            int m1 = m0 + wm * 32 + mt * 16 + gID;
#pragma unroll
            for (int nt = 0; nt < 4; nt++) {
                int n = n0 + wn * 32 + nt * 8 + tg * 2;
                int h = n >> 6, d = n & 63;
                float b0v = qb[n], b1v = qb[n + 1];
                float v0 = __fadd_rn(__fadd_rn(s_[mt][nt][0], c_[mt][nt][0]), b0v);
                float v1 = __fadd_rn(__fadd_rn(s_[mt][nt][1], c_[mt][nt][1]), b1v);
                float v2 = __fadd_rn(__fadd_rn(s_[mt][nt][2], c_[mt][nt][2]), b0v);
                float v3 = __fadd_rn(__fadd_rn(s_[mt][nt][3], c_[mt][nt][3]), b1v);
                int bb = m1 >> 10, t = m1 & 1023;
                *(float2*)&Q[(((size_t)(bb * H_ + h)) * T_ + t) * DH_ + d] = make_float2(v0, v1);
                int m2 = m1 + 8;
                int bb2 = m2 >> 10, t2 = m2 & 1023;
                *(float2*)&Q[(((size_t)(bb2 * H_ + h)) * T_ + t2) * DH_ + d] = make_float2(v2, v3);
            }
        }
    }
}

// ---------------- O GEMM with head-mask chunk skip (bf16 3-MMA) ----------------
__global__ __launch_bounds__(256) void gemm_o(
    const __nv_bfloat16* __restrict__ Ahi, const __nv_bfloat16* __restrict__ Alo,
    const __nv_bfloat16* __restrict__ Bhi, const __nv_bfloat16* __restrict__ Blo,
    const float* __restrict__ bias, float* __restrict__ Cout,
    const float* __restrict__ maskp)
{
    extern __shared__ char smc[];
    const int tid = threadIdx.x;
    const int lane = tid & 31, wid = tid >> 5;
    const int wm = wid >> 2, wn = wid & 3;
    const int gID = lane >> 2, tg = lane & 3;
    const int m0 = blockIdx.y * 128, n0 = blockIdx.x * 128;
    uint32_t sbase = (uint32_t)__cvta_generic_to_shared(smc);

    __shared__ int act[NCHUNK];
    __shared__ int s_na;
    if (tid == 0) {
        int n = 0;
        int b16 = (m0 >> 10) << 4;
        for (int ch = 0; ch < NCHUNK; ch++)
            if (maskp[b16 + (ch >> 1)] != 0.f) act[n++] = ch;
        s_na = n;
    }
    __syncthreads();
    const int na = s_na;

    float acc[4][4][4];
#pragma unroll
    for (int mt = 0; mt < 4; mt++)
#pragma unroll
        for (int nt = 0; nt < 4; nt++)
#pragma unroll
            for (int r = 0; r < 4; r++) acc[mt][nt][r] = 0.f;

    GEMM_MAINLOOP(ACT_LUT, na)

#pragma unroll
    for (int mt = 0; mt < 4; mt++) {
        int m1 = m0 + wm * 64 + mt * 16 + gID;
#pragma unroll
        for (int nt = 0; nt < 4; nt++) {
            int n = n0 + wn * 32 + nt * 8 + tg * 2;
            float b0v = bias[n], b1v = bias[n + 1];
            float* a = acc[mt][nt];
            *(float2*)&Cout[(size_t)m1 * C_ + n] = make_float2(a[0] + b0v, a[1] + b1v);
            *(float2*)&Cout[(size_t)(m1 + 8) * C_ + n] = make_float2(a[2] + b0v, a[3] + b1v);
        }
    }
}

// -------------- q post: RMS norm + exact top-k, emits bf16 split --------------
__global__ __launch_bounds__(256) void qpost(
    const float* __restrict__ q,
    __nv_bfloat16* __restrict__ qh, __nv_bfloat16* __restrict__ ql)
{
    int grp = threadIdx.x >> 6;
    int lane = threadIdx.x & 63;
    int row = blockIdx.x * 4 + grp;
    float v = q[(size_t)row * 64 + lane];
    float ss = v * v;
#pragma unroll
    for (int o = 16; o > 0; o >>= 1) ss += __shfl_xor_sync(0xffffffffu, ss, o);
    __shared__ float ws[8];
    if ((threadIdx.x & 31) == 0) ws[threadIdx.x >> 5] = ss;
    __syncthreads();
    float rms = sqrtf((ws[grp * 2] + ws[grp * 2 + 1]) * (1.f / 64.f)) + 1e-6f;
    float vn = v / rms;
    float a = fabsf(vn);
    __shared__ __align__(16) float sa[4][64];
    sa[grp][lane] = a;
    __syncthreads();
    int g = 0;
    const float4* sv = (const float4*)sa[grp];
#pragma unroll
    for (int j = 0; j < 16; j++) {
        float4 t = sv[j];
        g += (t.x > a) + (t.y > a) + (t.z > a) + (t.w > a);
    }
    int h = (row >> 10) & 15;
    int kc = KEEPC[h];
    float cand = (g <= kc - 1) ? a : INFINITY;
#pragma unroll
    for (int o = 16; o > 0; o >>= 1)
        cand = fminf(cand, __shfl_xor_sync(0xffffffffu, cand, o));
    __shared__ float wm_[8];
    if ((threadIdx.x & 31) == 0) wm_[threadIdx.x >> 5] = cand;
    __syncthreads();
    float th = fminf(wm_[grp * 2], wm_[grp * 2 + 1]);
    float vnm = (a >= th) ? vn : 0.f;
    __nv_bfloat16 hh = __float2bfloat16(vnm);
    qh[(size_t)row * 64 + lane] = hh;
    ql[(size_t)row * 64 + lane] = __float2bfloat16(vnm - __bfloat162float(hh));
}

// -------------- MMA flash attention (S bf16 3-MMA; PV fp16 2-MMA) --------------
#define APAD_B 144
#define ATS 9216
#define ATT_SMEM (2 * ATS + 2 * 4 * ATS)   // 92160

__device__ __forceinline__ void att_kvload(
    uint32_t sb, int s, int kt, size_t hoff, int tid,
    const __nv_bfloat16* __restrict__ kh_g, const __nv_bfloat16* __restrict__ kl_g,
    const __nv_bfloat16* __restrict__ vth_g, const __nv_bfloat16* __restrict__ vtl_g)
{
    uint32_t st = sb + 2 * ATS + s * 4 * ATS;
#pragma unroll
    for (int i = 0; i < 16; i++) {
        int u = tid + i * 128;
        int t = u >> 9, row = (u >> 3) & 63, c = u & 7;
        const __nv_bfloat16* src;
        if (t == 0)      src = kh_g + hoff + (size_t)(kt * 64 + row) * 64 + c * 8;
        else if (t == 1) src = kl_g + hoff + (size_t)(kt * 64 + row) * 64 + c * 8;
        else if (t == 2) src = vth_g + hoff + (size_t)row * T_ + kt * 64 + c * 8;
        else             src = vtl_g + hoff + (size_t)row * T_ + kt * 64 + c * 8;
        uint32_t dst = st + t * ATS + row * APAD_B + c * 16;
        asm volatile("cp.async.cg.shared.global [%0], [%1], 16;" :: "r"(dst), "l"(src));
    }
}

__global__ __launch_bounds__(128) void attn_mma(
    const __nv_bfloat16* __restrict__ qh_g, const __nv_bfloat16* __restrict__ ql_g,
    const __nv_bfloat16* __restrict__ kh_g, const __nv_bfloat16* __restrict__ kl_g,
    const __nv_bfloat16* __restrict__ vth_g, const __nv_bfloat16* __restrict__ vtl_g,
    __nv_bfloat16* __restrict__ aoh, __nv_bfloat16* __restrict__ aol,
    float* __restrict__ gepart)
{
    extern __shared__ char smr[];
    __shared__ float red[128];
    const int qt = (int)(gridDim.x - 1) - (int)blockIdx.x;   // heavy tiles first
    const int bh = blockIdx.y, q0 = qt * 64;
    const int tid = threadIdx.x, lane = tid & 31, w = tid >> 5;
    const int gID = lane >> 2, tg = lane & 3;
    uint32_t sb = (uint32_t)__cvta_generic_to_shared(smr);
    const size_t hoff = (size_t)bh * (T_ * 64);

#pragma unroll
    for (int i = 0; i < 8; i++) {
        int u = tid + i * 128;
        int t = u >> 9, row = (u >> 3) & 63, c = u & 7;
        const __nv_bfloat16* src = (t ? ql_g : qh_g) + hoff + (size_t)(q0 + row) * 64 + c * 8;
        uint32_t dst = sb + t * ATS + row * APAD_B + c * 16;
        asm volatile("cp.async.cg.shared.global [%0], [%1], 16;" :: "r"(dst), "l"(src));
    }
    att_kvload(sb, 0, 0, hoff, tid, kh_g, kl_g, vth_g, vtl_g);
    asm volatile("cp.async.commit_group;" ::: "memory");
    asm volatile("cp.async.wait_group 0;" ::: "memory");
    __syncthreads();

    float oacc[8][4];
#pragma unroll
    for (int nt = 0; nt < 8; nt++)
#pragma unroll
        for (int r = 0; r < 4; r++) oacc[nt][r] = 0.f;
    float mrow[2] = {-1e30f, -1e30f}, lrow[2] = {0.f, 0.f}, erow[2] = {0.f, 0.f};

    for (int kt = 0; kt <= qt; kt++) {
        if (kt < qt) {
            att_kvload(sb, (kt + 1) & 1, kt + 1, hoff, tid, kh_g, kl_g, vth_g, vtl_g);
            asm volatile("cp.async.commit_group;" ::: "memory");
        }
        uint32_t st = sb + 2 * ATS + (kt & 1) * 4 * ATS;

        float sacc[8][4];
#pragma unroll
        for (int nt = 0; nt < 8; nt++)
#pragma unroll
            for (int r = 0; r < 4; r++) sacc[nt][r] = 0.f;

#pragma unroll
        for (int ks = 0; ks < 4; ks++) {
            uint32_t aoff = sb + (w * 16 + gID) * APAD_B + (ks * 16 + tg * 2) * 2;
            uint32_t qh0 = *(const uint32_t*)(smr + (aoff - sb));
            uint32_t qh2 = *(const uint32_t*)(smr + (aoff - sb) + 16);
            uint32_t qh1 = *(const uint32_t*)(smr + (aoff - sb) + 8 * APAD_B);
            uint32_t qh3 = *(const uint32_t*)(smr + (aoff - sb) + 8 * APAD_B + 16);
            uint32_t ql0 = *(const uint32_t*)(smr + (aoff - sb) + ATS);
            uint32_t ql2 = *(const uint32_t*)(smr + (aoff - sb) + ATS + 16);
            uint32_t ql1 = *(const uint32_t*)(smr + (aoff - sb) + ATS + 8 * APAD_B);
            uint32_t ql3 = *(const uint32_t*)(smr + (aoff - sb) + ATS + 8 * APAD_B + 16);

            uint32_t kf[8][2];
#pragma unroll
            for (int nt = 0; nt < 8; nt++) {
                uint32_t bo = (st - sb) + (nt * 8 + gID) * APAD_B + (ks * 16 + tg * 2) * 2;
                kf[nt][0] = *(const uint32_t*)(smr + bo);
                kf[nt][1] = *(const uint32_t*)(smr + bo + 16);
            }
#pragma unroll
            for (int nt = 0; nt < 8; nt++)
                mma16816(sacc[nt], qh0, qh1, qh2, qh3, kf[nt][0], kf[nt][1]);
#pragma unroll
            for (int nt = 0; nt < 8; nt++)
                mma16816(sacc[nt], ql0, ql1, ql2, ql3, kf[nt][0], kf[nt][1]);
#pragma unroll
            for (int nt = 0; nt < 8; nt++) {
                uint32_t bo = (st - sb) + ATS + (nt * 8 + gID) * APAD_B + (ks * 16 + tg * 2) * 2;
                kf[nt][0] = *(const uint32_t*)(smr + bo);
                kf[nt][1] = *(const uint32_t*)(smr + bo + 16);
            }
#pragma unroll
            for (int nt = 0; nt < 8; nt++)
                mma16816(sacc[nt], qh0, qh1, qh2, qh3, kf[nt][0], kf[nt][1]);
        }

        if (kt == qt) {
            int r0 = w * 16 + gID, r1 = r0 + 8;
#pragma unroll
            for (int nt = 0; nt < 8; nt++) {
                int c0 = nt * 8 + tg * 2, c1 = c0 + 1;
                if (c0 > r0) sacc[nt][0] = -1e30f;
                if (c1 > r0) sacc[nt][1] = -1e30f;
                if (c0 > r1) sacc[nt][2] = -1e30f;
                if (c1 > r1) sacc[nt][3] = -1e30f;
            }
        }

#pragma unroll
        for (int r = 0; r < 2; r++) {
            float tm = -1e30f;
#pragma unroll
            for (int nt = 0; nt < 8; nt++)
                tm = fmaxf(tm, fmaxf(sacc[nt][2 * r], sacc[nt][2 * r + 1]));
            tm = fmaxf(tm, __shfl_xor_sync(0xffffffffu, tm, 1));
            tm = fmaxf(tm, __shfl_xor_sync(0xffffffffu, tm, 2));
            float mn = fmaxf(mrow[r], tm);
            float sc = fast_exp(mrow[r] - mn);
            mrow[r] = mn;
            float se = 0.f, s2 = 0.f;
#pragma unroll
            for (int nt = 0; nt < 8; nt++) {
                float p0 = fast_exp(sacc[nt][2 * r] - mn);
                float p1 = fast_exp(sacc[nt][2 * r + 1] - mn);
                sacc[nt][2 * r] = p0; sacc[nt][2 * r + 1] = p1;
                se += p0 + p1;
                s2 += p0 * p0 + p1 * p1;
            }
            se += __shfl_xor_sync(0xffffffffu, se, 1);
            se += __shfl_xor_sync(0xffffffffu, se, 2);
            s2 += __shfl_xor_sync(0xffffffffu, s2, 1);
            s2 += __shfl_xor_sync(0xffffffffu, s2, 2);
            lrow[r] = lrow[r] * sc + se;
            erow[r] = erow[r] * sc * sc + s2;
#pragma unroll
            for (int nt = 0; nt < 8; nt++) {
                oacc[nt][2 * r] *= sc;
                oacc[nt][2 * r + 1] *= sc;
            }
        }

        // PV: P single fp16, V fp16 hi/lo -> 2 MMA passes
#pragma unroll
        for (int ks = 0; ks < 4; ks++) {
            float* pa = sacc[2 * ks];
            float* pb = sacc[2 * ks + 1];
            uint32_t ph[4];
            ph[0] = pack_f16x2(pa[0], pa[1]);
            ph[1] = pack_f16x2(pa[2], pa[3]);
            ph[2] = pack_f16x2(pb[0], pb[1]);
            ph[3] = pack_f16x2(pb[2], pb[3]);

            uint32_t vf[8][2];
#pragma unroll
            for (int nt = 0; nt < 8; nt++) {
                uint32_t bo = (st - sb) + 2 * ATS + (nt * 8 + gID) * APAD_B + (ks * 16 + tg * 2) * 2;
                vf[nt][0] = *(const uint32_t*)(smr + bo);
                vf[nt][1] = *(const uint32_t*)(smr + bo + 16);
            }
#pragma unroll
            for (int nt = 0; nt < 8; nt++)
                mma16816h(oacc[nt], ph[0], ph[1], ph[2], ph[3], vf[nt][0], vf[nt][1]);
#pragma unroll
            for (int nt = 0; nt < 8; nt++) {
                uint32_t bo = (st - sb) + 3 * ATS + (nt * 8 + gID) * APAD_B + (ks * 16 + tg * 2) * 2;
                vf[nt][0] = *(const uint32_t*)(smr + bo);
                vf[nt][1] = *(const uint32_t*)(smr + bo + 16);
            }
#pragma unroll
            for (int nt = 0; nt < 8; nt++)
                mma16816h(oacc[nt], ph[0], ph[1], ph[2], ph[3], vf[nt][0], vf[nt][1]);
        }

        asm volatile("cp.async.wait_group 0;" ::: "memory");
        __syncthreads();
    }

    // epilogue: write bf16 hi/lo of out (unmasked; mask handled by O-GEMM chunk skip)
    float linv0 = 1.f / lrow[0], linv1 = 1.f / lrow[1];
    int r0 = w * 16 + gID, r1 = r0 + 8;
    int b = bh >> 4, h = bh & 15;
    size_t base0 = (size_t)(b * T_ + q0 + r0) * C_ + h * DH_;
    size_t base1 = (size_t)(b * T_ + q0 + r1) * C_ + h * DH_;
#pragma unroll
    for (int nt = 0; nt < 8; nt++) {
        int col = nt * 8 + tg * 2;
        float v0 = oacc[nt][0] * linv0, v1 = oacc[nt][1] * linv0;
        float v2 = oacc[nt][2] * linv1, v3 = oacc[nt][3] * linv1;
        ushort2 H0, L0, H1, L1;
        bf16split(v0, H0.x, L0.x); bf16split(v1, H0.y, L0.y);
        bf16split(v2, H1.x, L1.x); bf16split(v3, H1.y, L1.y);
        *(ushort2*)&aoh[base0 + col] = H0;
        *(ushort2*)&aol[base0 + col] = L0;
        *(ushort2*)&aoh[base1 + col] = H1;
        *(ushort2*)&aol[base1 + col] = L1;
    }

    red[tid] = (tg == 0) ? (erow[0] * linv0 * linv0 + erow[1] * linv1 * linv1) : 0.f;
    __syncthreads();
    for (int o = 64; o > 0; o >>= 1) {
        if (tid < o) red[tid] += red[tid + o];
        __syncthreads();
    }
    if (tid == 0) gepart[bh * 16 + qt] = red[0];
}

// -------------- head energy -> entropy -> adaptive head mask --------------
__global__ void headmask(const float* __restrict__ epart, float* __restrict__ maskout)
{
    __shared__ double e[64];
    __shared__ double cand[64];
    int t = threadIdx.x;
    double s = 0.0;
    for (int i = 0; i < 16; i++) s += (double)epart[t * 16 + i];
    e[t] = s / 1048576.0;
    __syncthreads();
    int b = t >> 4;
    double m = -1e300;
    for (int j = 0; j < 16; j++) m = fmax(m, e[b * 16 + j]);
    double Z = 0.0;
    for (int j = 0; j < 16; j++) Z += exp(e[b * 16 + j] - m);
    double ent = 0.0;
    for (int j = 0; j < 16; j++) {
        double p = exp(e[b * 16 + j] - m) / Z;
        ent -= p * log(p + 1e-9);
    }
    double entn = fmin(fmax(ent / log(16.0), 0.0), 1.0);
    int keep = (int)rint(2.0 + entn * 4.0);
    double eh = e[t];
    int g = 0;
    for (int j = 0; j < 16; j++) g += (e[b * 16 + j] > eh);
    cand[t] = (g <= keep - 1) ? eh : 1e300;
    __syncthreads();
    double th = 1e300;
    for (int j = 0; j < 16; j++) th = fmin(th, cand[b * 16 + j]);
    maskout[t] = (eh >= th) ? 1.f : 0.f;
}

// ---------------- launch ----------------
extern "C" void kernel_launch(void* const* d_in, const int* in_sizes, int n_in,
                              void* d_out, int out_size)
{
    const float* x  = (const float*)d_in[0];
    const float* qw = (const float*)d_in[1];
    const float* qb = (const float*)d_in[2];
    const float* kw = (const float*)d_in[3];
    const float* kb = (const float*)d_in[4];
    const float* vw = (const float*)d_in[5];
    const float* vb = (const float*)d_in[6];
    const float* ow = (const float*)d_in[7];
    const float* ob = (const float*)d_in[8];
    float* out = (float*)d_out;

    float *gq, *gep, *gm;
    cudaGetSymbolAddress((void**)&gq, g_q);
    cudaGetSymbolAddress((void**)&gep, g_epart);
    cudaGetSymbolAddress((void**)&gm, g_mask);

    __nv_bfloat16 *xh, *xl, *x3, *qws, *kwh, *kwl, *vwh, *vwl, *owh, *owl, *aoh, *aol;
    __nv_bfloat16 *qsh, *qsl, *ksh, *ksl, *vth, *vtl;
    unsigned short* xf;
    cudaGetSymbolAddress((void**)&xh, g_xh);   cudaGetSymbolAddress((void**)&xl, g_xl);
    cudaGetSymbolAddress((void**)&x3, g_x3);   cudaGetSymbolAddress((void**)&xf, g_xf);
    cudaGetSymbolAddress((void**)&qws, g_qws);
    cudaGetSymbolAddress((void**)&kwh, g_kwh); cudaGetSymbolAddress((void**)&kwl, g_kwl);
    cudaGetSymbolAddress((void**)&vwh, g_vwh); cudaGetSymbolAddress((void**)&vwl, g_vwl);
    cudaGetSymbolAddress((void**)&owh, g_owh); cudaGetSymbolAddress((void**)&owl, g_owl);
    cudaGetSymbolAddress((void**)&aoh, g_aoh); cudaGetSymbolAddress((void**)&aol, g_aol);
    cudaGetSymbolAddress((void**)&qsh, g_qsh); cudaGetSymbolAddress((void**)&qsl, g_qsl);
    cudaGetSymbolAddress((void**)&ksh, g_ksh); cudaGetSymbolAddress((void**)&ksl, g_ksl);
    cudaGetSymbolAddress((void**)&vth, g_vth); cudaGetSymbolAddress((void**)&vtl, g_vtl);

    cudaFuncSetAttribute((const void*)proj_fused,
                         cudaFuncAttributeMaxDynamicSharedMemorySize, 2 * STAGE_B);
    cudaFuncSetAttribute((const void*)gemm_o,
                         cudaFuncAttributeMaxDynamicSharedMemorySize, 2 * STAGE_B);
    cudaFuncSetAttribute((const void*)attn_mma,
                         cudaFuncAttributeMaxDynamicSharedMemorySize, ATT_SMEM);

    // fused prep: x splits (bf16 3-term + fp16 single) + weight preps (one launch)
    prep_fused<<<M_ * C_ / 1024 + 4 * (C_ * C_ / 1024), 256>>>(
        (const float4*)x, (const float4*)kw, (const float4*)vw,
        (const float4*)ow, (const float4*)qw,
        (ushort4*)xh, (ushort4*)xl, (ushort4*)x3, (ushort4*)xf,
        (ushort4*)kwh, (ushort4*)kwl, (ushort4*)vwh, (ushort4*)vwl,
        (ushort4*)owh, (ushort4*)owl, (ushort4*)qws);

    // fused projections: K (256) + V (256, fp16 2-MMA) + Q (512) CTAs in one launch
    proj_fused<<<1024, 256, 2 * STAGE_B>>>(
        xh, xl, x3, (const __nv_bfloat16*)xf, qws, kwh, kwl, vwh, vwl,
        qb, kb, vb, gq, ksh, ksl, vth, vtl);

    qpost<<<BH_ * T_ / 4, 256>>>(gq, qsh, qsl);

    attn_mma<<<dim3(16, BH_), 128, ATT_SMEM>>>(qsh, qsl, ksh, ksl, vth, vtl, aoh, aol, gep);
    headmask<<<1, 64>>>(gep, gm);

    dim3 tGrid(C_ / 128, M_ / 128);
    gemm_o<<<tGrid, 256, 2 * STAGE_B>>>(aoh, aol, owh, owl, ob, out, gm);
}